// round 12
// baseline (speedup 1.0000x reference)
#include <cuda_runtime.h>
#include <math.h>
#include <float.h>

#define BS    4096
#define LSEQ  200
#define VOCAB 100000
#define ESTR  130   // k_es EsmT u64 row stride ([e][128 row-pairs] + pad)
#define HS    68    // hisP float row stride

typedef unsigned long long u64;

// ---- packed fp32x2 helpers (Blackwell FFMA2 path) ----
__device__ __forceinline__ u64 pack2(float x, float y) {
    u64 r; asm("mov.b64 %0, {%1, %2};" : "=l"(r) : "f"(x), "f"(y)); return r;
}
__device__ __forceinline__ u64 pack_dup(float x) {
    u64 r; asm("mov.b64 %0, {%1, %1};" : "=l"(r) : "f"(x)); return r;
}
__device__ __forceinline__ void unpack2(u64 v, float& x, float& y) {
    asm("mov.b64 {%0, %1}, %2;" : "=f"(x), "=f"(y) : "l"(v));
}
__device__ __forceinline__ void ffma2(u64& d, u64 a, u64 b) {
    asm("fma.rn.f32x2 %0, %1, %2, %0;" : "+l"(d) : "l"(a), "l"(b));
}
__device__ __forceinline__ u64 fadd2(u64 a, u64 b) {
    u64 r; asm("add.rn.f32x2 %0, %1, %2;" : "=l"(r) : "l"(a), "l"(b)); return r;
}

// Scratch (allocation-free: device globals)
__device__ float g_ES[VOCAB * 64];            // 25.6 MB: E @ S, row 0 zeroed
__device__ float g_caps[BS * 4 * 64];         // 4 MB: routing output

// ---------------------------------------------------------------------------
// Kernel 1: ES = E @ S. 256 rows/CTA, thread tile 8 rows x 8 cols (row-pair
// packed FFMA2): 6 wf / 2048 MACs per warp-e-iter (half the L1 of R11).
// ---------------------------------------------------------------------------
__global__ __launch_bounds__(256, 2) void k_es(const float* __restrict__ E,
                                               const float* __restrict__ S) {
    extern __shared__ float sm[];
    float* Ssm  = sm;                        // 64*64 floats
    u64*   EsmT = (u64*)(sm + 4096);         // [64 e][130] u64 row-pairs
    const int tid = threadIdx.x;
    const int v0 = blockIdx.x * 256;

    for (int i = tid; i < 1024; i += 256)
        ((float4*)Ssm)[i] = ((const float4*)S)[i];
    // stage E as packed row-pairs, transposed to [e][rp]; 128 rp x 16 e4
    for (int i = tid; i < 2048; i += 256) {
        int rp = i >> 4, e4 = i & 15;
        int vA = v0 + 2 * rp, vB = vA + 1;
        float4 a = make_float4(0.f, 0.f, 0.f, 0.f), bv = a;
        if (vA < VOCAB) a  = *(const float4*)&E[(size_t)vA * 64 + e4 * 4];
        if (vB < VOCAB) bv = *(const float4*)&E[(size_t)vB * 64 + e4 * 4];
        EsmT[(4 * e4 + 0) * ESTR + rp] = pack2(a.x, bv.x);
        EsmT[(4 * e4 + 1) * ESTR + rp] = pack2(a.y, bv.y);
        EsmT[(4 * e4 + 2) * ESTR + rp] = pack2(a.z, bv.z);
        EsmT[(4 * e4 + 3) * ESTR + rp] = pack2(a.w, bv.w);
    }
    __syncthreads();

    const int vg = tid >> 3;   // 32 groups x 4 row-pairs (8 rows)
    const int dg = tid & 7;    // 8 groups x 8 cols
    u64 acc[4][8];             // [row-pair q][col c]
#pragma unroll
    for (int q = 0; q < 4; q++)
#pragma unroll
        for (int c = 0; c < 8; c++) acc[q][c] = 0ull;

#pragma unroll 2
    for (int e = 0; e < 64; e++) {
        float4 sv0 = *(float4*)&Ssm[e * 64 + dg * 8];
        float4 sv1 = *(float4*)&Ssm[e * 64 + dg * 8 + 4];
        u64 sd[8];
        sd[0] = pack_dup(sv0.x); sd[1] = pack_dup(sv0.y);
        sd[2] = pack_dup(sv0.z); sd[3] = pack_dup(sv0.w);
        sd[4] = pack_dup(sv1.x); sd[5] = pack_dup(sv1.y);
        sd[6] = pack_dup(sv1.z); sd[7] = pack_dup(sv1.w);
        ulonglong2 eA = *(ulonglong2*)&EsmT[e * ESTR + vg * 4];      // q=0,1
        ulonglong2 eB = *(ulonglong2*)&EsmT[e * ESTR + vg * 4 + 2];  // q=2,3
#pragma unroll
        for (int c = 0; c < 8; c++) {
            ffma2(acc[0][c], eA.x, sd[c]);
            ffma2(acc[1][c], eA.y, sd[c]);
            ffma2(acc[2][c], eB.x, sd[c]);
            ffma2(acc[3][c], eB.y, sd[c]);
        }
    }

#pragma unroll
    for (int q = 0; q < 4; q++) {
        int vA = v0 + (vg * 4 + q) * 2, vB = vA + 1;
        float oa[8], ob[8];
#pragma unroll
        for (int c = 0; c < 8; c++) unpack2(acc[q][c], oa[c], ob[c]);
        if (vA < VOCAB) {
            if (vA == 0)
#pragma unroll
                for (int c = 0; c < 8; c++) oa[c] = 0.f;   // padding_idx row
            *(float4*)&g_ES[(size_t)vA * 64 + dg * 8]     = make_float4(oa[0], oa[1], oa[2], oa[3]);
            *(float4*)&g_ES[(size_t)vA * 64 + dg * 8 + 4] = make_float4(oa[4], oa[5], oa[6], oa[7]);
        }
        if (vB < VOCAB) {
            *(float4*)&g_ES[(size_t)vB * 64 + dg * 8]     = make_float4(ob[0], ob[1], ob[2], ob[3]);
            *(float4*)&g_ES[(size_t)vB * 64 + dg * 8 + 4] = make_float4(ob[4], ob[5], ob[6], ob[7]);
        }
    }
}

// ---------------------------------------------------------------------------
// Kernel 2: routing (R11 champion, unchanged). One CTA/batch, 256 thr, 3/SM.
// ---------------------------------------------------------------------------
__global__ __launch_bounds__(256, 3) void k_route(const int* __restrict__ his,
                                                  const float* __restrict__ B0) {
    extern __shared__ u64 smu[];
    u64*   part2 = smu;                        // [8 lc][k*32+dp]  1024 u64
    u64*   capsP = part2 + 1024;               // [k][dp] pair-packed caps  128 u64
    float* hisP  = (float*)(capsP + 128);      // [200][68] floats
    float* Bk    = hisP + LSEQ * HS;           // [k][l] 800
    float* WkF   = Bk + 800;                   // [l][4k] plain exp floats  800+pad
    float* msum  = WkF + 816;                  // 8
    float* ssum  = msum + 8;                   // 8
    int*   idx   = (int*)(ssum + 8);           // 200

    const int tid  = threadIdx.x;
    const int b    = blockIdx.x;
    const int lane = tid & 31;
    const int w    = tid >> 5;
    const float DROPV = -2147483648.0f;

    for (int l = tid; l < LSEQ; l += 256) idx[l] = his[b * LSEQ + l];
    for (int t = tid; t < 4 * LSEQ; t += 256) Bk[t] = B0[t];
    __syncthreads();

    for (int t = tid; t < LSEQ * 16; t += 256) {
        int l = t >> 4, dq = t & 15;
        float4 v = *(const float4*)&g_ES[(size_t)idx[l] * 64 + dq * 4];
        *(float4*)&hisP[l * HS + dq * 4] = v;
    }
    __syncthreads();

    for (int it = 0; it < 3; it++) {
        // ---- split softmax: warp w handles k = w>>1, half = w&1 (100 l) ----
        {
            const int k = w >> 1;
            const int base = (w & 1) * 100;
            float m = -FLT_MAX;
            for (int j = lane; j < 100; j += 32) {
                int l = base + j;
                float v = (idx[l] != 0) ? Bk[k * LSEQ + l] : DROPV;
                m = fmaxf(m, v);
            }
#pragma unroll
            for (int o = 16; o > 0; o >>= 1) m = fmaxf(m, __shfl_xor_sync(0xffffffffu, m, o));
            float s = 0.f;
            for (int j = lane; j < 100; j += 32) {
                int l = base + j;
                float v = (idx[l] != 0) ? Bk[k * LSEQ + l] : DROPV;
                float e = __expf(v - m);
                WkF[l * 4 + k] = e;
                s += e;
            }
#pragma unroll
            for (int o = 16; o > 0; o >>= 1) s += __shfl_xor_sync(0xffffffffu, s, o);
            if (lane == 0) { msum[w] = m; ssum[w] = s; }
        }
        __syncthreads();

        // ---- caps partials: ALL 8 warps. warp = l-chunk (25 l), lane = dp ----
        {
            const int l0 = w * 25;
            u64 a0 = 0ull, a1 = 0ull, a2 = 0ull, a3 = 0ull;
#pragma unroll 5
            for (int j = 0; j < 25; j++) {
                const int l = l0 + j;
                u64 h2 = *(u64*)&hisP[l * HS + 2 * lane];   // LDS.64, conflict-free
                float4 wl = *(float4*)&WkF[l * 4];          // 1-wf broadcast
                ffma2(a0, h2, pack_dup(wl.x));
                ffma2(a1, h2, pack_dup(wl.y));
                ffma2(a2, h2, pack_dup(wl.z));
                ffma2(a3, h2, pack_dup(wl.w));
            }
            part2[w * 128 +  0 + lane] = a0;
            part2[w * 128 + 32 + lane] = a1;
            part2[w * 128 + 64 + lane] = a2;
            part2[w * 128 + 96 + lane] = a3;
        }
        __syncthreads();

        // ---- reduce (chunks 0-3 = half0, 4-7 = half1), combine, squash ----
        if (tid < 128) {
            const int k  = tid >> 5;
            const int dp = tid & 31;
            u64 cl = part2[k * 32 + dp];
#pragma unroll
            for (int lc = 1; lc < 4; lc++) cl = fadd2(cl, part2[lc * 128 + k * 32 + dp]);
            u64 ch = part2[4 * 128 + k * 32 + dp];
#pragma unroll
            for (int lc = 5; lc < 8; lc++) ch = fadd2(ch, part2[lc * 128 + k * 32 + dp]);

            float m0 = msum[2 * k], m1 = msum[2 * k + 1];
            float s0 = ssum[2 * k], s1 = ssum[2 * k + 1];
            float M  = fmaxf(m0, m1);
            float g0 = __expf(m0 - M), g1 = __expf(m1 - M);
            float Sinv = 1.f / (s0 * g0 + s1 * g1);
            float f0 = g0 * Sinv, f1 = g1 * Sinv;

            float lx, ly, hx, hy;
            unpack2(cl, lx, ly);
            unpack2(ch, hx, hy);
            float cx = lx * f0 + hx * f1;
            float cy = ly * f0 + hy * f1;

            float sq = cx * cx + cy * cy;
#pragma unroll
            for (int o = 16; o > 0; o >>= 1) sq += __shfl_xor_sync(0xffffffffu, sq, o);
            float n2 = sq;
            float n  = sqrtf(n2);
            float scale = n2 / ((1.f + n2) * n + 1e-9f);
            cx *= scale; cy *= scale;
            if (it == 2) {
                *(float2*)&g_caps[b * 256 + k * 64 + 2 * dp] = make_float2(cx, cy);
            } else {
                capsP[k * 32 + dp] = pack2(cx, cy);
            }
        }
        if (it == 2) break;
        __syncthreads();

        // ---- B[k][l] += dot(caps[k], hisP[l]) : thread-per-l, quad-wide ----
        {
            const int l = (tid < LSEQ) ? tid : (LSEQ - 1);
            u64 s0 = 0ull, s1 = 0ull, s2 = 0ull, s3 = 0ull;
#pragma unroll 4
            for (int dq = 0; dq < 16; dq++) {
                ulonglong2 h  = *(ulonglong2*)&hisP[l * HS + dq * 4];
                ulonglong2 c0 = *(ulonglong2*)&capsP[0 * 32 + 2 * dq];
                ulonglong2 c1 = *(ulonglong2*)&capsP[1 * 32 + 2 * dq];
                ulonglong2 c2 = *(ulonglong2*)&capsP[2 * 32 + 2 * dq];
                ulonglong2 c3 = *(ulonglong2*)&capsP[3 * 32 + 2 * dq];
                ffma2(s0, h.x, c0.x); ffma2(s0, h.y, c0.y);
                ffma2(s1, h.x, c1.x); ffma2(s1, h.y, c1.y);
                ffma2(s2, h.x, c2.x); ffma2(s2, h.y, c2.y);
                ffma2(s3, h.x, c3.x); ffma2(s3, h.y, c3.y);
            }
            if (tid < LSEQ) {
                float x, y;
                unpack2(s0, x, y); Bk[0 * LSEQ + l] += x + y;
                unpack2(s1, x, y); Bk[1 * LSEQ + l] += x + y;
                unpack2(s2, x, y); Bk[2 * LSEQ + l] += x + y;
                unpack2(s3, x, y); Bk[3 * LSEQ + l] += x + y;
            }
        }
        __syncthreads();
    }
}

// ---------------------------------------------------------------------------
// Kernel 3: batched MLP. 512 CTAs x 32 rows, f-chunked 4x64 (unchanged).
// ---------------------------------------------------------------------------
__global__ __launch_bounds__(256, 4) void k_mlp(const float* __restrict__ W1,
                                                const float* __restrict__ b1,
                                                const float* __restrict__ W2,
                                                const float* __restrict__ b2,
                                                float* __restrict__ out) {
    extern __shared__ float sm[];
    float* W1c = sm;                 // 64*64
    float* W2c = W1c + 4096;         // 64*64
    float* cs  = W2c + 4096;         // 32*65
    float* hs  = cs + 32 * 65;       // 32*68
    float* b1s = hs + 32 * 68;       // 256
    float* b2s = b1s + 256;          // 64
    const int tid  = threadIdx.x;
    const int row0 = blockIdx.x * 32;

    for (int i = tid; i < 2048; i += 256) {
        int r = i >> 6, e = i & 63;
        cs[r * 65 + e] = g_caps[row0 * 64 + i];
    }
    if (tid < 256) b1s[tid] = b1[tid];
    if (tid < 64)  b2s[tid] = b2[tid];

    const int rq = tid >> 4;
    const int dq = tid & 15;
    u64 acc2[2][2];
    acc2[0][0] = acc2[0][1] = acc2[1][0] = acc2[1][1] = 0ull;

    for (int ch = 0; ch < 4; ch++) {
        const int f0 = ch * 64;
        __syncthreads();
        for (int i4 = tid; i4 < 1024; i4 += 256) {
            int e = i4 >> 4, j4 = i4 & 15;
            ((float4*)W1c)[i4] = *(const float4*)&W1[e * 256 + f0 + j4 * 4];
        }
        for (int i4 = tid; i4 < 1024; i4 += 256)
            ((float4*)W2c)[i4] = ((const float4*)&W2[f0 * 64])[i4];
        __syncthreads();

        {
            u64 acc1[2][2];
            acc1[0][0] = acc1[0][1] = acc1[1][0] = acc1[1][1] = 0ull;
#pragma unroll 4
            for (int e = 0; e < 64; e++) {
                u64 cd0 = pack_dup(cs[(rq * 2 + 0) * 65 + e]);
                u64 cd1 = pack_dup(cs[(rq * 2 + 1) * 65 + e]);
                ulonglong2 wv = *(ulonglong2*)&W1c[e * 64 + dq * 4];
                ffma2(acc1[0][0], cd0, wv.x); ffma2(acc1[0][1], cd0, wv.y);
                ffma2(acc1[1][0], cd1, wv.x); ffma2(acc1[1][1], cd1, wv.y);
            }
            float4 bb = *(float4*)&b1s[f0 + dq * 4];
#pragma unroll
            for (int i = 0; i < 2; i++) {
                float4 h; float x, y;
                unpack2(acc1[i][0], x, y); h.x = fmaxf(x + bb.x, 0.f); h.y = fmaxf(y + bb.y, 0.f);
                unpack2(acc1[i][1], x, y); h.z = fmaxf(x + bb.z, 0.f); h.w = fmaxf(y + bb.w, 0.f);
                *(float4*)&hs[(rq * 2 + i) * 68 + dq * 4] = h;
            }
        }
        __syncthreads();

#pragma unroll 4
        for (int f = 0; f < 64; f++) {
            u64 hd0 = pack_dup(hs[(rq * 2 + 0) * 68 + f]);
            u64 hd1 = pack_dup(hs[(rq * 2 + 1) * 68 + f]);
            ulonglong2 wv = *(ulonglong2*)&W2c[f * 64 + dq * 4];
            ffma2(acc2[0][0], hd0, wv.x); ffma2(acc2[0][1], hd0, wv.y);
            ffma2(acc2[1][0], hd1, wv.x); ffma2(acc2[1][1], hd1, wv.y);
        }
    }

    float4 bb = *(float4*)&b2s[dq * 4];
#pragma unroll
    for (int i = 0; i < 2; i++) {
        float4 o; float x, y;
        unpack2(acc2[i][0], x, y); o.x = x + bb.x; o.y = y + bb.y;
        unpack2(acc2[i][1], x, y); o.z = x + bb.z; o.w = y + bb.w;
        *(float4*)&out[(size_t)(row0 + rq * 2 + i) * 64 + dq * 4] = o;
    }
}

// ---------------------------------------------------------------------------
static const int SMEM1 = 4096 * 4 + 64 * ESTR * 8;                              // 82,944 B
static const int SMEM2 = (1024 + 128) * 8 + (LSEQ * HS + 800 + 816 + 16) * 4 + LSEQ * 4; // 70,944 B
static const int SMEM3 = (4096 + 4096 + 32 * 65 + 32 * 68 + 256 + 64) * 4;      // 51,072 B

extern "C" void kernel_launch(void* const* d_in, const int* in_sizes, int n_in,
                              void* d_out, int out_size) {
    const int*   his = (const int*)  d_in[0];
    const float* E   = (const float*)d_in[1];
    const float* S   = (const float*)d_in[2];
    const float* B0  = (const float*)d_in[3];
    const float* W1  = (const float*)d_in[4];
    const float* b1  = (const float*)d_in[5];
    const float* W2  = (const float*)d_in[6];
    const float* b2  = (const float*)d_in[7];
    float* out = (float*)d_out;

    cudaFuncSetAttribute(k_es,    cudaFuncAttributeMaxDynamicSharedMemorySize, SMEM1);
    cudaFuncSetAttribute(k_route, cudaFuncAttributeMaxDynamicSharedMemorySize, SMEM2);
    cudaFuncSetAttribute(k_mlp,   cudaFuncAttributeMaxDynamicSharedMemorySize, SMEM3);

    k_es<<<(VOCAB + 255) / 256, 256, SMEM1>>>(E, S);
    k_route<<<BS, 256, SMEM2>>>(his, B0);
    k_mlp<<<(BS * 4) / 32, 256, SMEM3>>>(W1, b1, W2, b2, out);
}

// round 13
// speedup vs baseline: 1.0237x; 1.0237x over previous
#include <cuda_runtime.h>
#include <math.h>
#include <float.h>

#define BS    4096
#define LSEQ  200
#define VOCAB 100000
#define ESTR  66    // k_es EsmT u64 row stride
#define HS    68    // hisP float row stride

typedef unsigned long long u64;

// ---- packed fp32x2 helpers (Blackwell FFMA2 path) ----
__device__ __forceinline__ u64 pack2(float x, float y) {
    u64 r; asm("mov.b64 %0, {%1, %2};" : "=l"(r) : "f"(x), "f"(y)); return r;
}
__device__ __forceinline__ u64 pack_dup(float x) {
    u64 r; asm("mov.b64 %0, {%1, %1};" : "=l"(r) : "f"(x)); return r;
}
__device__ __forceinline__ void unpack2(u64 v, float& x, float& y) {
    asm("mov.b64 {%0, %1}, %2;" : "=f"(x), "=f"(y) : "l"(v));
}
__device__ __forceinline__ void ffma2(u64& d, u64 a, u64 b) {
    asm("fma.rn.f32x2 %0, %1, %2, %0;" : "+l"(d) : "l"(a), "l"(b));
}
__device__ __forceinline__ u64 fadd2(u64 a, u64 b) {
    u64 r; asm("add.rn.f32x2 %0, %1, %2;" : "=l"(r) : "l"(a), "l"(b)); return r;
}

// Scratch (allocation-free: device globals)
__device__ float g_ES[VOCAB * 64];            // 25.6 MB: E @ S, row 0 zeroed
__device__ float g_caps[BS * 4 * 64];         // 4 MB: routing output

// ---------------------------------------------------------------------------
// Kernel 1: ES = E @ S. R11 config: 128 rows/CTA, 8x4 row-pair tile, 4 CTA/SM.
// ---------------------------------------------------------------------------
__global__ __launch_bounds__(256, 4) void k_es(const float* __restrict__ E,
                                               const float* __restrict__ S) {
    extern __shared__ float sm[];
    float* Ssm  = sm;                        // 64*64
    u64*   EsmT = (u64*)(sm + 4096);         // [64 e][66] u64 row-pairs
    const int tid = threadIdx.x;
    const int v0 = blockIdx.x * 128;

    for (int i = tid; i < 1024; i += 256)
        ((float4*)Ssm)[i] = ((const float4*)S)[i];
    for (int i = tid; i < 1024; i += 256) {
        int rp = i >> 4, e4 = i & 15;
        int vA = v0 + 2 * rp, vB = vA + 1;
        float4 a = make_float4(0.f, 0.f, 0.f, 0.f), bv = a;
        if (vA < VOCAB) a  = *(const float4*)&E[(size_t)vA * 64 + e4 * 4];
        if (vB < VOCAB) bv = *(const float4*)&E[(size_t)vB * 64 + e4 * 4];
        EsmT[(4 * e4 + 0) * ESTR + rp] = pack2(a.x, bv.x);
        EsmT[(4 * e4 + 1) * ESTR + rp] = pack2(a.y, bv.y);
        EsmT[(4 * e4 + 2) * ESTR + rp] = pack2(a.z, bv.z);
        EsmT[(4 * e4 + 3) * ESTR + rp] = pack2(a.w, bv.w);
    }
    __syncthreads();

    const int vg = tid >> 4;
    const int dg = tid & 15;
    u64 acc[4][4];
#pragma unroll
    for (int q = 0; q < 4; q++)
#pragma unroll
        for (int c = 0; c < 4; c++) acc[q][c] = 0ull;

#pragma unroll 4
    for (int e = 0; e < 64; e++) {
        float4 sv = *(float4*)&Ssm[e * 64 + dg * 4];
        u64 sd[4];
        sd[0] = pack_dup(sv.x); sd[1] = pack_dup(sv.y);
        sd[2] = pack_dup(sv.z); sd[3] = pack_dup(sv.w);
        ulonglong2 eA = *(ulonglong2*)&EsmT[e * ESTR + vg * 4];
        ulonglong2 eB = *(ulonglong2*)&EsmT[e * ESTR + vg * 4 + 2];
#pragma unroll
        for (int c = 0; c < 4; c++) {
            ffma2(acc[0][c], eA.x, sd[c]);
            ffma2(acc[1][c], eA.y, sd[c]);
            ffma2(acc[2][c], eB.x, sd[c]);
            ffma2(acc[3][c], eB.y, sd[c]);
        }
    }

#pragma unroll
    for (int q = 0; q < 4; q++) {
        int vA = v0 + vg * 8 + 2 * q, vB = vA + 1;
        float4 oa, ob;
        unpack2(acc[q][0], oa.x, ob.x);
        unpack2(acc[q][1], oa.y, ob.y);
        unpack2(acc[q][2], oa.z, ob.z);
        unpack2(acc[q][3], oa.w, ob.w);
        if (vA < VOCAB) {
            if (vA == 0) oa = make_float4(0.f, 0.f, 0.f, 0.f);
            *(float4*)&g_ES[(size_t)vA * 64 + dg * 4] = oa;
        }
        if (vB < VOCAB) {
            *(float4*)&g_ES[(size_t)vB * 64 + dg * 4] = ob;
        }
    }
}

// ---------------------------------------------------------------------------
// Kernel 2: routing (R11 champion, unchanged). One CTA/batch, 256 thr, 3/SM.
// ---------------------------------------------------------------------------
__global__ __launch_bounds__(256, 3) void k_route(const int* __restrict__ his,
                                                  const float* __restrict__ B0) {
    extern __shared__ u64 smu[];
    u64*   part2 = smu;                        // [8 lc][k*32+dp]  1024 u64
    u64*   capsP = part2 + 1024;               // [k][dp] pair-packed caps  128 u64
    float* hisP  = (float*)(capsP + 128);      // [200][68] floats
    float* Bk    = hisP + LSEQ * HS;           // [k][l] 800
    float* WkF   = Bk + 800;                   // [l][4k] plain exp floats  800+pad
    float* msum  = WkF + 816;                  // 8
    float* ssum  = msum + 8;                   // 8
    int*   idx   = (int*)(ssum + 8);           // 200

    const int tid  = threadIdx.x;
    const int b    = blockIdx.x;
    const int lane = tid & 31;
    const int w    = tid >> 5;
    const float DROPV = -2147483648.0f;

    for (int l = tid; l < LSEQ; l += 256) idx[l] = his[b * LSEQ + l];
    for (int t = tid; t < 4 * LSEQ; t += 256) Bk[t] = B0[t];
    __syncthreads();

    for (int t = tid; t < LSEQ * 16; t += 256) {
        int l = t >> 4, dq = t & 15;
        float4 v = *(const float4*)&g_ES[(size_t)idx[l] * 64 + dq * 4];
        *(float4*)&hisP[l * HS + dq * 4] = v;
    }
    __syncthreads();

    for (int it = 0; it < 3; it++) {
        // ---- split softmax: warp w handles k = w>>1, half = w&1 (100 l) ----
        {
            const int k = w >> 1;
            const int base = (w & 1) * 100;
            float m = -FLT_MAX;
            for (int j = lane; j < 100; j += 32) {
                int l = base + j;
                float v = (idx[l] != 0) ? Bk[k * LSEQ + l] : DROPV;
                m = fmaxf(m, v);
            }
#pragma unroll
            for (int o = 16; o > 0; o >>= 1) m = fmaxf(m, __shfl_xor_sync(0xffffffffu, m, o));
            float s = 0.f;
            for (int j = lane; j < 100; j += 32) {
                int l = base + j;
                float v = (idx[l] != 0) ? Bk[k * LSEQ + l] : DROPV;
                float e = __expf(v - m);
                WkF[l * 4 + k] = e;
                s += e;
            }
#pragma unroll
            for (int o = 16; o > 0; o >>= 1) s += __shfl_xor_sync(0xffffffffu, s, o);
            if (lane == 0) { msum[w] = m; ssum[w] = s; }
        }
        __syncthreads();

        // ---- caps partials: ALL 8 warps. warp = l-chunk (25 l), lane = dp ----
        {
            const int l0 = w * 25;
            u64 a0 = 0ull, a1 = 0ull, a2 = 0ull, a3 = 0ull;
#pragma unroll 5
            for (int j = 0; j < 25; j++) {
                const int l = l0 + j;
                u64 h2 = *(u64*)&hisP[l * HS + 2 * lane];   // LDS.64, conflict-free
                float4 wl = *(float4*)&WkF[l * 4];          // 1-wf broadcast
                ffma2(a0, h2, pack_dup(wl.x));
                ffma2(a1, h2, pack_dup(wl.y));
                ffma2(a2, h2, pack_dup(wl.z));
                ffma2(a3, h2, pack_dup(wl.w));
            }
            part2[w * 128 +  0 + lane] = a0;
            part2[w * 128 + 32 + lane] = a1;
            part2[w * 128 + 64 + lane] = a2;
            part2[w * 128 + 96 + lane] = a3;
        }
        __syncthreads();

        // ---- reduce (chunks 0-3 = half0, 4-7 = half1), combine, squash ----
        if (tid < 128) {
            const int k  = tid >> 5;
            const int dp = tid & 31;
            u64 cl = part2[k * 32 + dp];
#pragma unroll
            for (int lc = 1; lc < 4; lc++) cl = fadd2(cl, part2[lc * 128 + k * 32 + dp]);
            u64 ch = part2[4 * 128 + k * 32 + dp];
#pragma unroll
            for (int lc = 5; lc < 8; lc++) ch = fadd2(ch, part2[lc * 128 + k * 32 + dp]);

            float m0 = msum[2 * k], m1 = msum[2 * k + 1];
            float s0 = ssum[2 * k], s1 = ssum[2 * k + 1];
            float M  = fmaxf(m0, m1);
            float g0 = __expf(m0 - M), g1 = __expf(m1 - M);
            float Sinv = 1.f / (s0 * g0 + s1 * g1);
            float f0 = g0 * Sinv, f1 = g1 * Sinv;

            float lx, ly, hx, hy;
            unpack2(cl, lx, ly);
            unpack2(ch, hx, hy);
            float cx = lx * f0 + hx * f1;
            float cy = ly * f0 + hy * f1;

            float sq = cx * cx + cy * cy;
#pragma unroll
            for (int o = 16; o > 0; o >>= 1) sq += __shfl_xor_sync(0xffffffffu, sq, o);
            float n2 = sq;
            float n  = sqrtf(n2);
            float scale = n2 / ((1.f + n2) * n + 1e-9f);
            cx *= scale; cy *= scale;
            if (it == 2) {
                *(float2*)&g_caps[b * 256 + k * 64 + 2 * dp] = make_float2(cx, cy);
            } else {
                capsP[k * 32 + dp] = pack2(cx, cy);
            }
        }
        if (it == 2) break;
        __syncthreads();

        // ---- B[k][l] += dot(caps[k], hisP[l]) : thread-per-l, quad-wide ----
        {
            const int l = (tid < LSEQ) ? tid : (LSEQ - 1);
            u64 s0 = 0ull, s1 = 0ull, s2 = 0ull, s3 = 0ull;
#pragma unroll 4
            for (int dq = 0; dq < 16; dq++) {
                ulonglong2 h  = *(ulonglong2*)&hisP[l * HS + dq * 4];
                ulonglong2 c0 = *(ulonglong2*)&capsP[0 * 32 + 2 * dq];
                ulonglong2 c1 = *(ulonglong2*)&capsP[1 * 32 + 2 * dq];
                ulonglong2 c2 = *(ulonglong2*)&capsP[2 * 32 + 2 * dq];
                ulonglong2 c3 = *(ulonglong2*)&capsP[3 * 32 + 2 * dq];
                ffma2(s0, h.x, c0.x); ffma2(s0, h.y, c0.y);
                ffma2(s1, h.x, c1.x); ffma2(s1, h.y, c1.y);
                ffma2(s2, h.x, c2.x); ffma2(s2, h.y, c2.y);
                ffma2(s3, h.x, c3.x); ffma2(s3, h.y, c3.y);
            }
            if (tid < LSEQ) {
                float x, y;
                unpack2(s0, x, y); Bk[0 * LSEQ + l] += x + y;
                unpack2(s1, x, y); Bk[1 * LSEQ + l] += x + y;
                unpack2(s2, x, y); Bk[2 * LSEQ + l] += x + y;
                unpack2(s3, x, y); Bk[3 * LSEQ + l] += x + y;
            }
        }
        __syncthreads();
    }
}

// ---------------------------------------------------------------------------
// Kernel 3: batched MLP. 512 CTAs x 32 rows; launch_bounds(256,3) -> NO SPILL.
// ---------------------------------------------------------------------------
__global__ __launch_bounds__(256, 3) void k_mlp(const float* __restrict__ W1,
                                                const float* __restrict__ b1,
                                                const float* __restrict__ W2,
                                                const float* __restrict__ b2,
                                                float* __restrict__ out) {
    extern __shared__ float sm[];
    float* W1c = sm;                 // 64*64
    float* W2c = W1c + 4096;         // 64*64
    float* cs  = W2c + 4096;         // 32*65
    float* hs  = cs + 32 * 65;       // 32*68
    float* b1s = hs + 32 * 68;       // 256
    float* b2s = b1s + 256;          // 64
    const int tid  = threadIdx.x;
    const int row0 = blockIdx.x * 32;

    for (int i = tid; i < 2048; i += 256) {
        int r = i >> 6, e = i & 63;
        cs[r * 65 + e] = g_caps[row0 * 64 + i];
    }
    if (tid < 256) b1s[tid] = b1[tid];
    if (tid < 64)  b2s[tid] = b2[tid];

    const int rq = tid >> 4;
    const int dq = tid & 15;
    u64 acc2[2][2];
    acc2[0][0] = acc2[0][1] = acc2[1][0] = acc2[1][1] = 0ull;

    for (int ch = 0; ch < 4; ch++) {
        const int f0 = ch * 64;
        __syncthreads();
        for (int i4 = tid; i4 < 1024; i4 += 256) {
            int e = i4 >> 4, j4 = i4 & 15;
            ((float4*)W1c)[i4] = *(const float4*)&W1[e * 256 + f0 + j4 * 4];
        }
        for (int i4 = tid; i4 < 1024; i4 += 256)
            ((float4*)W2c)[i4] = ((const float4*)&W2[f0 * 64])[i4];
        __syncthreads();

        {
            u64 acc1[2][2];
            acc1[0][0] = acc1[0][1] = acc1[1][0] = acc1[1][1] = 0ull;
#pragma unroll 4
            for (int e = 0; e < 64; e++) {
                u64 cd0 = pack_dup(cs[(rq * 2 + 0) * 65 + e]);
                u64 cd1 = pack_dup(cs[(rq * 2 + 1) * 65 + e]);
                ulonglong2 wv = *(ulonglong2*)&W1c[e * 64 + dq * 4];
                ffma2(acc1[0][0], cd0, wv.x); ffma2(acc1[0][1], cd0, wv.y);
                ffma2(acc1[1][0], cd1, wv.x); ffma2(acc1[1][1], cd1, wv.y);
            }
            float4 bb = *(float4*)&b1s[f0 + dq * 4];
#pragma unroll
            for (int i = 0; i < 2; i++) {
                float4 h; float x, y;
                unpack2(acc1[i][0], x, y); h.x = fmaxf(x + bb.x, 0.f); h.y = fmaxf(y + bb.y, 0.f);
                unpack2(acc1[i][1], x, y); h.z = fmaxf(x + bb.z, 0.f); h.w = fmaxf(y + bb.w, 0.f);
                *(float4*)&hs[(rq * 2 + i) * 68 + dq * 4] = h;
            }
        }
        __syncthreads();

#pragma unroll 4
        for (int f = 0; f < 64; f++) {
            u64 hd0 = pack_dup(hs[(rq * 2 + 0) * 68 + f]);
            u64 hd1 = pack_dup(hs[(rq * 2 + 1) * 68 + f]);
            ulonglong2 wv = *(ulonglong2*)&W2c[f * 64 + dq * 4];
            ffma2(acc2[0][0], hd0, wv.x); ffma2(acc2[0][1], hd0, wv.y);
            ffma2(acc2[1][0], hd1, wv.x); ffma2(acc2[1][1], hd1, wv.y);
        }
    }

    float4 bb = *(float4*)&b2s[dq * 4];
#pragma unroll
    for (int i = 0; i < 2; i++) {
        float4 o; float x, y;
        unpack2(acc2[i][0], x, y); o.x = x + bb.x; o.y = y + bb.y;
        unpack2(acc2[i][1], x, y); o.z = x + bb.z; o.w = y + bb.w;
        *(float4*)&out[(size_t)(row0 + rq * 2 + i) * 64 + dq * 4] = o;
    }
}

// ---------------------------------------------------------------------------
static const int SMEM1 = 4096 * 4 + 64 * ESTR * 8;                              // 50,176 B
static const int SMEM2 = (1024 + 128) * 8 + (LSEQ * HS + 800 + 816 + 16) * 4 + LSEQ * 4; // 70,944 B
static const int SMEM3 = (4096 + 4096 + 32 * 65 + 32 * 68 + 256 + 64) * 4;      // 51,072 B

extern "C" void kernel_launch(void* const* d_in, const int* in_sizes, int n_in,
                              void* d_out, int out_size) {
    const int*   his = (const int*)  d_in[0];
    const float* E   = (const float*)d_in[1];
    const float* S   = (const float*)d_in[2];
    const float* B0  = (const float*)d_in[3];
    const float* W1  = (const float*)d_in[4];
    const float* b1  = (const float*)d_in[5];
    const float* W2  = (const float*)d_in[6];
    const float* b2  = (const float*)d_in[7];
    float* out = (float*)d_out;

    cudaFuncSetAttribute(k_es,    cudaFuncAttributeMaxDynamicSharedMemorySize, SMEM1);
    cudaFuncSetAttribute(k_route, cudaFuncAttributeMaxDynamicSharedMemorySize, SMEM2);
    cudaFuncSetAttribute(k_mlp,   cudaFuncAttributeMaxDynamicSharedMemorySize, SMEM3);

    k_es<<<(VOCAB + 127) / 128, 256, SMEM1>>>(E, S);
    k_route<<<BS, 256, SMEM2>>>(his, B0);
    k_mlp<<<(BS * 4) / 32, 256, SMEM3>>>(W1, b1, W2, b2, out);
}

// round 14
// speedup vs baseline: 1.0290x; 1.0051x over previous
#include <cuda_runtime.h>
#include <math.h>
#include <float.h>

#define BS    4096
#define LSEQ  200
#define VOCAB 100000
#define ESTR  66    // k_es EsmT u64 row stride
#define HS    68    // hisP float row stride

typedef unsigned long long u64;

// ---- packed fp32x2 helpers (Blackwell FFMA2 path) ----
__device__ __forceinline__ u64 pack2(float x, float y) {
    u64 r; asm("mov.b64 %0, {%1, %2};" : "=l"(r) : "f"(x), "f"(y)); return r;
}
__device__ __forceinline__ u64 pack_dup(float x) {
    u64 r; asm("mov.b64 %0, {%1, %1};" : "=l"(r) : "f"(x)); return r;
}
__device__ __forceinline__ void unpack2(u64 v, float& x, float& y) {
    asm("mov.b64 {%0, %1}, %2;" : "=f"(x), "=f"(y) : "l"(v));
}
__device__ __forceinline__ void ffma2(u64& d, u64 a, u64 b) {
    asm("fma.rn.f32x2 %0, %1, %2, %0;" : "+l"(d) : "l"(a), "l"(b));
}
__device__ __forceinline__ u64 fadd2(u64 a, u64 b) {
    u64 r; asm("add.rn.f32x2 %0, %1, %2;" : "=l"(r) : "l"(a), "l"(b)); return r;
}

// Scratch (allocation-free: device globals)
__device__ float g_ES[VOCAB * 64];            // 25.6 MB: E @ S, row 0 zeroed
__device__ float g_caps[BS * 4 * 64];         // 4 MB: routing output

// ---------------------------------------------------------------------------
// Kernel 1: ES = E @ S (champion config, unchanged).
// ---------------------------------------------------------------------------
__global__ __launch_bounds__(256, 4) void k_es(const float* __restrict__ E,
                                               const float* __restrict__ S) {
    extern __shared__ float sm[];
    float* Ssm  = sm;                        // 64*64
    u64*   EsmT = (u64*)(sm + 4096);         // [64 e][66] u64 row-pairs
    const int tid = threadIdx.x;
    const int v0 = blockIdx.x * 128;

    for (int i = tid; i < 1024; i += 256)
        ((float4*)Ssm)[i] = ((const float4*)S)[i];
    for (int i = tid; i < 1024; i += 256) {
        int rp = i >> 4, e4 = i & 15;
        int vA = v0 + 2 * rp, vB = vA + 1;
        float4 a = make_float4(0.f, 0.f, 0.f, 0.f), bv = a;
        if (vA < VOCAB) a  = *(const float4*)&E[(size_t)vA * 64 + e4 * 4];
        if (vB < VOCAB) bv = *(const float4*)&E[(size_t)vB * 64 + e4 * 4];
        EsmT[(4 * e4 + 0) * ESTR + rp] = pack2(a.x, bv.x);
        EsmT[(4 * e4 + 1) * ESTR + rp] = pack2(a.y, bv.y);
        EsmT[(4 * e4 + 2) * ESTR + rp] = pack2(a.z, bv.z);
        EsmT[(4 * e4 + 3) * ESTR + rp] = pack2(a.w, bv.w);
    }
    __syncthreads();

    const int vg = tid >> 4;
    const int dg = tid & 15;
    u64 acc[4][4];
#pragma unroll
    for (int q = 0; q < 4; q++)
#pragma unroll
        for (int c = 0; c < 4; c++) acc[q][c] = 0ull;

#pragma unroll 4
    for (int e = 0; e < 64; e++) {
        float4 sv = *(float4*)&Ssm[e * 64 + dg * 4];
        u64 sd[4];
        sd[0] = pack_dup(sv.x); sd[1] = pack_dup(sv.y);
        sd[2] = pack_dup(sv.z); sd[3] = pack_dup(sv.w);
        ulonglong2 eA = *(ulonglong2*)&EsmT[e * ESTR + vg * 4];
        ulonglong2 eB = *(ulonglong2*)&EsmT[e * ESTR + vg * 4 + 2];
#pragma unroll
        for (int c = 0; c < 4; c++) {
            ffma2(acc[0][c], eA.x, sd[c]);
            ffma2(acc[1][c], eA.y, sd[c]);
            ffma2(acc[2][c], eB.x, sd[c]);
            ffma2(acc[3][c], eB.y, sd[c]);
        }
    }

#pragma unroll
    for (int q = 0; q < 4; q++) {
        int vA = v0 + vg * 8 + 2 * q, vB = vA + 1;
        float4 oa, ob;
        unpack2(acc[q][0], oa.x, ob.x);
        unpack2(acc[q][1], oa.y, ob.y);
        unpack2(acc[q][2], oa.z, ob.z);
        unpack2(acc[q][3], oa.w, ob.w);
        if (vA < VOCAB) {
            if (vA == 0) oa = make_float4(0.f, 0.f, 0.f, 0.f);
            *(float4*)&g_ES[(size_t)vA * 64 + dg * 4] = oa;
        }
        if (vB < VOCAB) {
            *(float4*)&g_ES[(size_t)vB * 64 + dg * 4] = ob;
        }
    }
}

// ---------------------------------------------------------------------------
// Kernel 2: routing (champion, unchanged). One CTA/batch, 256 thr, 3/SM.
// ---------------------------------------------------------------------------
__global__ __launch_bounds__(256, 3) void k_route(const int* __restrict__ his,
                                                  const float* __restrict__ B0) {
    extern __shared__ u64 smu[];
    u64*   part2 = smu;                        // [8 lc][k*32+dp]  1024 u64
    u64*   capsP = part2 + 1024;               // [k][dp] pair-packed caps  128 u64
    float* hisP  = (float*)(capsP + 128);      // [200][68] floats
    float* Bk    = hisP + LSEQ * HS;           // [k][l] 800
    float* WkF   = Bk + 800;                   // [l][4k] plain exp floats  800+pad
    float* msum  = WkF + 816;                  // 8
    float* ssum  = msum + 8;                   // 8
    int*   idx   = (int*)(ssum + 8);           // 200

    const int tid  = threadIdx.x;
    const int b    = blockIdx.x;
    const int lane = tid & 31;
    const int w    = tid >> 5;
    const float DROPV = -2147483648.0f;

    for (int l = tid; l < LSEQ; l += 256) idx[l] = his[b * LSEQ + l];
    for (int t = tid; t < 4 * LSEQ; t += 256) Bk[t] = B0[t];
    __syncthreads();

    for (int t = tid; t < LSEQ * 16; t += 256) {
        int l = t >> 4, dq = t & 15;
        float4 v = *(const float4*)&g_ES[(size_t)idx[l] * 64 + dq * 4];
        *(float4*)&hisP[l * HS + dq * 4] = v;
    }
    __syncthreads();

    for (int it = 0; it < 3; it++) {
        // ---- split softmax: warp w handles k = w>>1, half = w&1 (100 l) ----
        {
            const int k = w >> 1;
            const int base = (w & 1) * 100;
            float m = -FLT_MAX;
            for (int j = lane; j < 100; j += 32) {
                int l = base + j;
                float v = (idx[l] != 0) ? Bk[k * LSEQ + l] : DROPV;
                m = fmaxf(m, v);
            }
#pragma unroll
            for (int o = 16; o > 0; o >>= 1) m = fmaxf(m, __shfl_xor_sync(0xffffffffu, m, o));
            float s = 0.f;
            for (int j = lane; j < 100; j += 32) {
                int l = base + j;
                float v = (idx[l] != 0) ? Bk[k * LSEQ + l] : DROPV;
                float e = __expf(v - m);
                WkF[l * 4 + k] = e;
                s += e;
            }
#pragma unroll
            for (int o = 16; o > 0; o >>= 1) s += __shfl_xor_sync(0xffffffffu, s, o);
            if (lane == 0) { msum[w] = m; ssum[w] = s; }
        }
        __syncthreads();

        // ---- caps partials: ALL 8 warps. warp = l-chunk (25 l), lane = dp ----
        {
            const int l0 = w * 25;
            u64 a0 = 0ull, a1 = 0ull, a2 = 0ull, a3 = 0ull;
#pragma unroll 5
            for (int j = 0; j < 25; j++) {
                const int l = l0 + j;
                u64 h2 = *(u64*)&hisP[l * HS + 2 * lane];   // LDS.64, conflict-free
                float4 wl = *(float4*)&WkF[l * 4];          // 1-wf broadcast
                ffma2(a0, h2, pack_dup(wl.x));
                ffma2(a1, h2, pack_dup(wl.y));
                ffma2(a2, h2, pack_dup(wl.z));
                ffma2(a3, h2, pack_dup(wl.w));
            }
            part2[w * 128 +  0 + lane] = a0;
            part2[w * 128 + 32 + lane] = a1;
            part2[w * 128 + 64 + lane] = a2;
            part2[w * 128 + 96 + lane] = a3;
        }
        __syncthreads();

        // ---- reduce (chunks 0-3 = half0, 4-7 = half1), combine, squash ----
        if (tid < 128) {
            const int k  = tid >> 5;
            const int dp = tid & 31;
            u64 cl = part2[k * 32 + dp];
#pragma unroll
            for (int lc = 1; lc < 4; lc++) cl = fadd2(cl, part2[lc * 128 + k * 32 + dp]);
            u64 ch = part2[4 * 128 + k * 32 + dp];
#pragma unroll
            for (int lc = 5; lc < 8; lc++) ch = fadd2(ch, part2[lc * 128 + k * 32 + dp]);

            float m0 = msum[2 * k], m1 = msum[2 * k + 1];
            float s0 = ssum[2 * k], s1 = ssum[2 * k + 1];
            float M  = fmaxf(m0, m1);
            float g0 = __expf(m0 - M), g1 = __expf(m1 - M);
            float Sinv = 1.f / (s0 * g0 + s1 * g1);
            float f0 = g0 * Sinv, f1 = g1 * Sinv;

            float lx, ly, hx, hy;
            unpack2(cl, lx, ly);
            unpack2(ch, hx, hy);
            float cx = lx * f0 + hx * f1;
            float cy = ly * f0 + hy * f1;

            float sq = cx * cx + cy * cy;
#pragma unroll
            for (int o = 16; o > 0; o >>= 1) sq += __shfl_xor_sync(0xffffffffu, sq, o);
            float n2 = sq;
            float n  = sqrtf(n2);
            float scale = n2 / ((1.f + n2) * n + 1e-9f);
            cx *= scale; cy *= scale;
            if (it == 2) {
                *(float2*)&g_caps[b * 256 + k * 64 + 2 * dp] = make_float2(cx, cy);
            } else {
                capsP[k * 32 + dp] = pack2(cx, cy);
            }
        }
        if (it == 2) break;
        __syncthreads();

        // ---- B[k][l] += dot(caps[k], hisP[l]) : thread-per-l, quad-wide ----
        {
            const int l = (tid < LSEQ) ? tid : (LSEQ - 1);
            u64 s0 = 0ull, s1 = 0ull, s2 = 0ull, s3 = 0ull;
#pragma unroll 4
            for (int dq = 0; dq < 16; dq++) {
                ulonglong2 h  = *(ulonglong2*)&hisP[l * HS + dq * 4];
                ulonglong2 c0 = *(ulonglong2*)&capsP[0 * 32 + 2 * dq];
                ulonglong2 c1 = *(ulonglong2*)&capsP[1 * 32 + 2 * dq];
                ulonglong2 c2 = *(ulonglong2*)&capsP[2 * 32 + 2 * dq];
                ulonglong2 c3 = *(ulonglong2*)&capsP[3 * 32 + 2 * dq];
                ffma2(s0, h.x, c0.x); ffma2(s0, h.y, c0.y);
                ffma2(s1, h.x, c1.x); ffma2(s1, h.y, c1.y);
                ffma2(s2, h.x, c2.x); ffma2(s2, h.y, c2.y);
                ffma2(s3, h.x, c3.x); ffma2(s3, h.y, c3.y);
            }
            if (tid < LSEQ) {
                float x, y;
                unpack2(s0, x, y); Bk[0 * LSEQ + l] += x + y;
                unpack2(s1, x, y); Bk[1 * LSEQ + l] += x + y;
                unpack2(s2, x, y); Bk[2 * LSEQ + l] += x + y;
                unpack2(s3, x, y); Bk[3 * LSEQ + l] += x + y;
            }
        }
        __syncthreads();
    }
}

// ---------------------------------------------------------------------------
// Kernel 3: batched MLP, ROW-PAIR PACKED. 512 CTAs x 32 rows, f-chunked 4x64.
// Thread (rp, dq): row-pair rp (2 rows, packed u64), cols dq*4..dq*4+3.
// Inner loop: 1 LDS.64 bcast + 1 LDS.128 + 4 dup + 4 FFMA2 = 512 warp-MACs/3wf.
// ---------------------------------------------------------------------------
__global__ __launch_bounds__(256, 4) void k_mlp(const float* __restrict__ W1,
                                                const float* __restrict__ b1,
                                                const float* __restrict__ W2,
                                                const float* __restrict__ b2,
                                                float* __restrict__ out) {
    extern __shared__ float sm[];
    float* W1c  = sm;                          // [64 e][64 f]  16KB
    float* W2c  = W1c + 4096;                  // [64 f][64 d]  16KB
    u64*   csPu = (u64*)(W2c + 4096);          // [16 rp][65 e] u64 pairs  8.3KB
    u64*   hsPu = csPu + 16 * 65;              // [16 rp][68 f] u64 pairs  8.7KB
    float* b1s  = (float*)(hsPu + 16 * 68);    // 256
    float* b2s  = b1s + 256;                   // 64
    const int tid  = threadIdx.x;
    const int row0 = blockIdx.x * 32;

    // Stage caps pair-packed: thread i -> (rp = i>>4, e4 = i&15)
    {
        const int rp = tid >> 4, e4 = tid & 15;
        float4 a = *(const float4*)&g_caps[(size_t)(row0 + 2 * rp) * 64 + e4 * 4];
        float4 c = *(const float4*)&g_caps[(size_t)(row0 + 2 * rp + 1) * 64 + e4 * 4];
        csPu[rp * 65 + e4 * 4 + 0] = pack2(a.x, c.x);
        csPu[rp * 65 + e4 * 4 + 1] = pack2(a.y, c.y);
        csPu[rp * 65 + e4 * 4 + 2] = pack2(a.z, c.z);
        csPu[rp * 65 + e4 * 4 + 3] = pack2(a.w, c.w);
    }
    if (tid < 256) b1s[tid] = b1[tid];
    if (tid < 64)  b2s[tid] = b2[tid];

    const int rp = tid >> 4;   // 16 row-pairs
    const int dq = tid & 15;   // 16 col-quads
    u64 acc2[4];
    acc2[0] = acc2[1] = acc2[2] = acc2[3] = 0ull;

    for (int ch = 0; ch < 4; ch++) {
        const int f0 = ch * 64;
        __syncthreads();
        for (int i4 = tid; i4 < 1024; i4 += 256) {
            int e = i4 >> 4, j4 = i4 & 15;
            ((float4*)W1c)[i4] = *(const float4*)&W1[e * 256 + f0 + j4 * 4];
        }
        for (int i4 = tid; i4 < 1024; i4 += 256)
            ((float4*)W2c)[i4] = ((const float4*)&W2[f0 * 64])[i4];
        __syncthreads();

        // GEMM1: h[rp-pair][f0+dq*4+c] = sum_e csPu * W1c  (+b1, relu)
        {
            u64 acc1[4];
            acc1[0] = acc1[1] = acc1[2] = acc1[3] = 0ull;
#pragma unroll 4
            for (int e = 0; e < 64; e++) {
                u64 cp = csPu[rp * 65 + e];                  // 1-wf broadcast
                float4 wv = *(float4*)&W1c[e * 64 + dq * 4]; // 2 wf
                ffma2(acc1[0], cp, pack_dup(wv.x));
                ffma2(acc1[1], cp, pack_dup(wv.y));
                ffma2(acc1[2], cp, pack_dup(wv.z));
                ffma2(acc1[3], cp, pack_dup(wv.w));
            }
#pragma unroll
            for (int c = 0; c < 4; c++) {
                float x, y;
                unpack2(acc1[c], x, y);
                float bb = b1s[f0 + dq * 4 + c];
                x = fmaxf(x + bb, 0.f);
                y = fmaxf(y + bb, 0.f);
                hsPu[rp * 68 + dq * 4 + c] = pack2(x, y);
            }
        }
        __syncthreads();

        // GEMM2 accumulate: out[rp-pair][dq*4+c] += sum_f hsPu * W2c
#pragma unroll 4
        for (int f = 0; f < 64; f++) {
            u64 hp = hsPu[rp * 68 + f];                      // 1-wf broadcast
            float4 wv = *(float4*)&W2c[f * 64 + dq * 4];     // 2 wf
            ffma2(acc2[0], hp, pack_dup(wv.x));
            ffma2(acc2[1], hp, pack_dup(wv.y));
            ffma2(acc2[2], hp, pack_dup(wv.z));
            ffma2(acc2[3], hp, pack_dup(wv.w));
        }
    }

    // Epilogue: unpack row-pair, add bias, store two float4 rows.
    float4 oa, ob;
    float4 bb = *(float4*)&b2s[dq * 4];
    unpack2(acc2[0], oa.x, ob.x);
    unpack2(acc2[1], oa.y, ob.y);
    unpack2(acc2[2], oa.z, ob.z);
    unpack2(acc2[3], oa.w, ob.w);
    oa.x += bb.x; oa.y += bb.y; oa.z += bb.z; oa.w += bb.w;
    ob.x += bb.x; ob.y += bb.y; ob.z += bb.z; ob.w += bb.w;
    *(float4*)&out[(size_t)(row0 + 2 * rp) * 64 + dq * 4]     = oa;
    *(float4*)&out[(size_t)(row0 + 2 * rp + 1) * 64 + dq * 4] = ob;
}

// ---------------------------------------------------------------------------
static const int SMEM1 = 4096 * 4 + 64 * ESTR * 8;                              // 50,176 B
static const int SMEM2 = (1024 + 128) * 8 + (LSEQ * HS + 800 + 816 + 16) * 4 + LSEQ * 4; // 70,944 B
static const int SMEM3 = 4096 * 4 * 2 + (16 * 65 + 16 * 68) * 8 + (256 + 64) * 4; // 51,072 B

extern "C" void kernel_launch(void* const* d_in, const int* in_sizes, int n_in,
                              void* d_out, int out_size) {
    const int*   his = (const int*)  d_in[0];
    const float* E   = (const float*)d_in[1];
    const float* S   = (const float*)d_in[2];
    const float* B0  = (const float*)d_in[3];
    const float* W1  = (const float*)d_in[4];
    const float* b1  = (const float*)d_in[5];
    const float* W2  = (const float*)d_in[6];
    const float* b2  = (const float*)d_in[7];
    float* out = (float*)d_out;

    cudaFuncSetAttribute(k_es,    cudaFuncAttributeMaxDynamicSharedMemorySize, SMEM1);
    cudaFuncSetAttribute(k_route, cudaFuncAttributeMaxDynamicSharedMemorySize, SMEM2);
    cudaFuncSetAttribute(k_mlp,   cudaFuncAttributeMaxDynamicSharedMemorySize, SMEM3);

    k_es<<<(VOCAB + 127) / 128, 256, SMEM1>>>(E, S);
    k_route<<<BS, 256, SMEM2>>>(his, B0);
    k_mlp<<<(BS * 4) / 32, 256, SMEM3>>>(W1, b1, W2, b2, out);
}

// round 15
// speedup vs baseline: 1.1131x; 1.0818x over previous
#include <cuda_runtime.h>
#include <math.h>
#include <float.h>

#define BS    4096
#define LSEQ  200
#define VOCAB 100000
#define ESTR  66    // k_es EsmT u64 row stride
#define HS    68    // hisP float row stride

typedef unsigned long long u64;

// ---- packed fp32x2 helpers (Blackwell FFMA2 path) ----
__device__ __forceinline__ u64 pack2(float x, float y) {
    u64 r; asm("mov.b64 %0, {%1, %2};" : "=l"(r) : "f"(x), "f"(y)); return r;
}
__device__ __forceinline__ u64 pack_dup(float x) {
    u64 r; asm("mov.b64 %0, {%1, %1};" : "=l"(r) : "f"(x)); return r;
}
__device__ __forceinline__ void unpack2(u64 v, float& x, float& y) {
    asm("mov.b64 {%0, %1}, %2;" : "=f"(x), "=f"(y) : "l"(v));
}
__device__ __forceinline__ void ffma2(u64& d, u64 a, u64 b) {
    asm("fma.rn.f32x2 %0, %1, %2, %0;" : "+l"(d) : "l"(a), "l"(b));
}
__device__ __forceinline__ u64 fadd2(u64 a, u64 b) {
    u64 r; asm("add.rn.f32x2 %0, %1, %2;" : "=l"(r) : "l"(a), "l"(b)); return r;
}

// Scratch (allocation-free: device globals)
__device__ float g_ES[VOCAB * 64];            // 25.6 MB: E @ S, row 0 zeroed
__device__ float g_caps[BS * 4 * 64];         // 4 MB: routing output

// ---------------------------------------------------------------------------
// Kernel 1: ES = E @ S (champion config, unchanged).
// ---------------------------------------------------------------------------
__global__ __launch_bounds__(256, 4) void k_es(const float* __restrict__ E,
                                               const float* __restrict__ S) {
    extern __shared__ float sm[];
    float* Ssm  = sm;                        // 64*64
    u64*   EsmT = (u64*)(sm + 4096);         // [64 e][66] u64 row-pairs
    const int tid = threadIdx.x;
    const int v0 = blockIdx.x * 128;

    for (int i = tid; i < 1024; i += 256)
        ((float4*)Ssm)[i] = ((const float4*)S)[i];
    for (int i = tid; i < 1024; i += 256) {
        int rp = i >> 4, e4 = i & 15;
        int vA = v0 + 2 * rp, vB = vA + 1;
        float4 a = make_float4(0.f, 0.f, 0.f, 0.f), bv = a;
        if (vA < VOCAB) a  = *(const float4*)&E[(size_t)vA * 64 + e4 * 4];
        if (vB < VOCAB) bv = *(const float4*)&E[(size_t)vB * 64 + e4 * 4];
        EsmT[(4 * e4 + 0) * ESTR + rp] = pack2(a.x, bv.x);
        EsmT[(4 * e4 + 1) * ESTR + rp] = pack2(a.y, bv.y);
        EsmT[(4 * e4 + 2) * ESTR + rp] = pack2(a.z, bv.z);
        EsmT[(4 * e4 + 3) * ESTR + rp] = pack2(a.w, bv.w);
    }
    __syncthreads();

    const int vg = tid >> 4;
    const int dg = tid & 15;
    u64 acc[4][4];
#pragma unroll
    for (int q = 0; q < 4; q++)
#pragma unroll
        for (int c = 0; c < 4; c++) acc[q][c] = 0ull;

#pragma unroll 4
    for (int e = 0; e < 64; e++) {
        float4 sv = *(float4*)&Ssm[e * 64 + dg * 4];
        u64 sd[4];
        sd[0] = pack_dup(sv.x); sd[1] = pack_dup(sv.y);
        sd[2] = pack_dup(sv.z); sd[3] = pack_dup(sv.w);
        ulonglong2 eA = *(ulonglong2*)&EsmT[e * ESTR + vg * 4];
        ulonglong2 eB = *(ulonglong2*)&EsmT[e * ESTR + vg * 4 + 2];
#pragma unroll
        for (int c = 0; c < 4; c++) {
            ffma2(acc[0][c], eA.x, sd[c]);
            ffma2(acc[1][c], eA.y, sd[c]);
            ffma2(acc[2][c], eB.x, sd[c]);
            ffma2(acc[3][c], eB.y, sd[c]);
        }
    }

#pragma unroll
    for (int q = 0; q < 4; q++) {
        int vA = v0 + vg * 8 + 2 * q, vB = vA + 1;
        float4 oa, ob;
        unpack2(acc[q][0], oa.x, ob.x);
        unpack2(acc[q][1], oa.y, ob.y);
        unpack2(acc[q][2], oa.z, ob.z);
        unpack2(acc[q][3], oa.w, ob.w);
        if (vA < VOCAB) {
            if (vA == 0) oa = make_float4(0.f, 0.f, 0.f, 0.f);
            *(float4*)&g_ES[(size_t)vA * 64 + dg * 4] = oa;
        }
        if (vB < VOCAB) {
            *(float4*)&g_ES[(size_t)vB * 64 + dg * 4] = ob;
        }
    }
}

// ---------------------------------------------------------------------------
// Kernel 2: routing (champion, unchanged). One CTA/batch, 256 thr, 3/SM.
// ---------------------------------------------------------------------------
__global__ __launch_bounds__(256, 3) void k_route(const int* __restrict__ his,
                                                  const float* __restrict__ B0) {
    extern __shared__ u64 smu[];
    u64*   part2 = smu;                        // [8 lc][k*32+dp]  1024 u64
    u64*   capsP = part2 + 1024;               // [k][dp] pair-packed caps  128 u64
    float* hisP  = (float*)(capsP + 128);      // [200][68] floats
    float* Bk    = hisP + LSEQ * HS;           // [k][l] 800
    float* WkF   = Bk + 800;                   // [l][4k] plain exp floats  800+pad
    float* msum  = WkF + 816;                  // 8
    float* ssum  = msum + 8;                   // 8
    int*   idx   = (int*)(ssum + 8);           // 200

    const int tid  = threadIdx.x;
    const int b    = blockIdx.x;
    const int lane = tid & 31;
    const int w    = tid >> 5;
    const float DROPV = -2147483648.0f;

    for (int l = tid; l < LSEQ; l += 256) idx[l] = his[b * LSEQ + l];
    for (int t = tid; t < 4 * LSEQ; t += 256) Bk[t] = B0[t];
    __syncthreads();

    for (int t = tid; t < LSEQ * 16; t += 256) {
        int l = t >> 4, dq = t & 15;
        float4 v = *(const float4*)&g_ES[(size_t)idx[l] * 64 + dq * 4];
        *(float4*)&hisP[l * HS + dq * 4] = v;
    }
    __syncthreads();

    for (int it = 0; it < 3; it++) {
        // ---- split softmax: warp w handles k = w>>1, half = w&1 (100 l) ----
        {
            const int k = w >> 1;
            const int base = (w & 1) * 100;
            float m = -FLT_MAX;
            for (int j = lane; j < 100; j += 32) {
                int l = base + j;
                float v = (idx[l] != 0) ? Bk[k * LSEQ + l] : DROPV;
                m = fmaxf(m, v);
            }
#pragma unroll
            for (int o = 16; o > 0; o >>= 1) m = fmaxf(m, __shfl_xor_sync(0xffffffffu, m, o));
            float s = 0.f;
            for (int j = lane; j < 100; j += 32) {
                int l = base + j;
                float v = (idx[l] != 0) ? Bk[k * LSEQ + l] : DROPV;
                float e = __expf(v - m);
                WkF[l * 4 + k] = e;
                s += e;
            }
#pragma unroll
            for (int o = 16; o > 0; o >>= 1) s += __shfl_xor_sync(0xffffffffu, s, o);
            if (lane == 0) { msum[w] = m; ssum[w] = s; }
        }
        __syncthreads();

        // ---- caps partials: ALL 8 warps. warp = l-chunk (25 l), lane = dp ----
        {
            const int l0 = w * 25;
            u64 a0 = 0ull, a1 = 0ull, a2 = 0ull, a3 = 0ull;
#pragma unroll 5
            for (int j = 0; j < 25; j++) {
                const int l = l0 + j;
                u64 h2 = *(u64*)&hisP[l * HS + 2 * lane];   // LDS.64, conflict-free
                float4 wl = *(float4*)&WkF[l * 4];          // 1-wf broadcast
                ffma2(a0, h2, pack_dup(wl.x));
                ffma2(a1, h2, pack_dup(wl.y));
                ffma2(a2, h2, pack_dup(wl.z));
                ffma2(a3, h2, pack_dup(wl.w));
            }
            part2[w * 128 +  0 + lane] = a0;
            part2[w * 128 + 32 + lane] = a1;
            part2[w * 128 + 64 + lane] = a2;
            part2[w * 128 + 96 + lane] = a3;
        }
        __syncthreads();

        // ---- reduce (chunks 0-3 = half0, 4-7 = half1), combine, squash ----
        if (tid < 128) {
            const int k  = tid >> 5;
            const int dp = tid & 31;
            u64 cl = part2[k * 32 + dp];
#pragma unroll
            for (int lc = 1; lc < 4; lc++) cl = fadd2(cl, part2[lc * 128 + k * 32 + dp]);
            u64 ch = part2[4 * 128 + k * 32 + dp];
#pragma unroll
            for (int lc = 5; lc < 8; lc++) ch = fadd2(ch, part2[lc * 128 + k * 32 + dp]);

            float m0 = msum[2 * k], m1 = msum[2 * k + 1];
            float s0 = ssum[2 * k], s1 = ssum[2 * k + 1];
            float M  = fmaxf(m0, m1);
            float g0 = __expf(m0 - M), g1 = __expf(m1 - M);
            float Sinv = 1.f / (s0 * g0 + s1 * g1);
            float f0 = g0 * Sinv, f1 = g1 * Sinv;

            float lx, ly, hx, hy;
            unpack2(cl, lx, ly);
            unpack2(ch, hx, hy);
            float cx = lx * f0 + hx * f1;
            float cy = ly * f0 + hy * f1;

            float sq = cx * cx + cy * cy;
#pragma unroll
            for (int o = 16; o > 0; o >>= 1) sq += __shfl_xor_sync(0xffffffffu, sq, o);
            float n2 = sq;
            float n  = sqrtf(n2);
            float scale = n2 / ((1.f + n2) * n + 1e-9f);
            cx *= scale; cy *= scale;
            if (it == 2) {
                *(float2*)&g_caps[b * 256 + k * 64 + 2 * dp] = make_float2(cx, cy);
            } else {
                capsP[k * 32 + dp] = pack2(cx, cy);
            }
        }
        if (it == 2) break;
        __syncthreads();

        // ---- B[k][l] += dot(caps[k], hisP[l]) : thread-per-l, quad-wide ----
        {
            const int l = (tid < LSEQ) ? tid : (LSEQ - 1);
            u64 s0 = 0ull, s1 = 0ull, s2 = 0ull, s3 = 0ull;
#pragma unroll 4
            for (int dq = 0; dq < 16; dq++) {
                ulonglong2 h  = *(ulonglong2*)&hisP[l * HS + dq * 4];
                ulonglong2 c0 = *(ulonglong2*)&capsP[0 * 32 + 2 * dq];
                ulonglong2 c1 = *(ulonglong2*)&capsP[1 * 32 + 2 * dq];
                ulonglong2 c2 = *(ulonglong2*)&capsP[2 * 32 + 2 * dq];
                ulonglong2 c3 = *(ulonglong2*)&capsP[3 * 32 + 2 * dq];
                ffma2(s0, h.x, c0.x); ffma2(s0, h.y, c0.y);
                ffma2(s1, h.x, c1.x); ffma2(s1, h.y, c1.y);
                ffma2(s2, h.x, c2.x); ffma2(s2, h.y, c2.y);
                ffma2(s3, h.x, c3.x); ffma2(s3, h.y, c3.y);
            }
            if (tid < LSEQ) {
                float x, y;
                unpack2(s0, x, y); Bk[0 * LSEQ + l] += x + y;
                unpack2(s1, x, y); Bk[1 * LSEQ + l] += x + y;
                unpack2(s2, x, y); Bk[2 * LSEQ + l] += x + y;
                unpack2(s3, x, y); Bk[3 * LSEQ + l] += x + y;
            }
        }
        __syncthreads();
    }
}

// ---------------------------------------------------------------------------
// Kernel 3: batched MLP. 256 CTAs x 64 rows; thread = 2 row-pairs x 4 cols.
// Per e-iter: 2 LDS.64 bcast + 2wf W-load = 4 wf / 512 warp-MACs.
// ---------------------------------------------------------------------------
__global__ __launch_bounds__(256, 3) void k_mlp(const float* __restrict__ W1,
                                                const float* __restrict__ b1,
                                                const float* __restrict__ W2,
                                                const float* __restrict__ b2,
                                                float* __restrict__ out) {
    extern __shared__ float sm[];
    float* W1c  = sm;                          // [64 e][64 f]  16KB
    float* W2c  = W1c + 4096;                  // [64 f][64 d]  16KB
    u64*   csPu = (u64*)(W2c + 4096);          // [32 rp][65 e] u64 pairs  16.6KB
    u64*   hsPu = csPu + 32 * 65;              // [32 rp][68 f] u64 pairs  17.4KB
    float* b1s  = (float*)(hsPu + 32 * 68);    // 256
    float* b2s  = b1s + 256;                   // 64
    const int tid  = threadIdx.x;
    const int row0 = blockIdx.x * 64;

    // Stage caps pair-packed: 512 items (32 rp x 16 e4), 2 per thread
    for (int i = tid; i < 512; i += 256) {
        const int rp = i >> 4, e4 = i & 15;
        float4 a = *(const float4*)&g_caps[(size_t)(row0 + 2 * rp) * 64 + e4 * 4];
        float4 c = *(const float4*)&g_caps[(size_t)(row0 + 2 * rp + 1) * 64 + e4 * 4];
        csPu[rp * 65 + e4 * 4 + 0] = pack2(a.x, c.x);
        csPu[rp * 65 + e4 * 4 + 1] = pack2(a.y, c.y);
        csPu[rp * 65 + e4 * 4 + 2] = pack2(a.z, c.z);
        csPu[rp * 65 + e4 * 4 + 3] = pack2(a.w, c.w);
    }
    if (tid < 256) b1s[tid] = b1[tid];
    if (tid < 64)  b2s[tid] = b2[tid];

    const int rq = tid >> 4;   // 16 groups -> row-pairs 2rq, 2rq+1 (4 rows)
    const int dq = tid & 15;   // 16 col-quads
    u64 acc2[2][4];
#pragma unroll
    for (int p = 0; p < 2; p++)
#pragma unroll
        for (int c = 0; c < 4; c++) acc2[p][c] = 0ull;

    for (int ch = 0; ch < 4; ch++) {
        const int f0 = ch * 64;
        __syncthreads();
        for (int i4 = tid; i4 < 1024; i4 += 256) {
            int e = i4 >> 4, j4 = i4 & 15;
            ((float4*)W1c)[i4] = *(const float4*)&W1[e * 256 + f0 + j4 * 4];
        }
        for (int i4 = tid; i4 < 1024; i4 += 256)
            ((float4*)W2c)[i4] = ((const float4*)&W2[f0 * 64])[i4];
        __syncthreads();

        // GEMM1: h = cs @ W1c (+b1, relu), 2 row-pairs per thread
        {
            u64 acc1[2][4];
#pragma unroll
            for (int p = 0; p < 2; p++)
#pragma unroll
                for (int c = 0; c < 4; c++) acc1[p][c] = 0ull;
#pragma unroll 4
            for (int e = 0; e < 64; e++) {
                u64 cp0 = csPu[(2 * rq) * 65 + e];           // 1-wf bcast
                u64 cp1 = csPu[(2 * rq + 1) * 65 + e];       // 1-wf bcast
                float4 wv = *(float4*)&W1c[e * 64 + dq * 4]; // 2 wf
                u64 w0 = pack_dup(wv.x), w1 = pack_dup(wv.y);
                u64 w2 = pack_dup(wv.z), w3 = pack_dup(wv.w);
                ffma2(acc1[0][0], cp0, w0); ffma2(acc1[0][1], cp0, w1);
                ffma2(acc1[0][2], cp0, w2); ffma2(acc1[0][3], cp0, w3);
                ffma2(acc1[1][0], cp1, w0); ffma2(acc1[1][1], cp1, w1);
                ffma2(acc1[1][2], cp1, w2); ffma2(acc1[1][3], cp1, w3);
            }
#pragma unroll
            for (int p = 0; p < 2; p++)
#pragma unroll
                for (int c = 0; c < 4; c++) {
                    float x, y;
                    unpack2(acc1[p][c], x, y);
                    float bb = b1s[f0 + dq * 4 + c];
                    x = fmaxf(x + bb, 0.f);
                    y = fmaxf(y + bb, 0.f);
                    hsPu[(2 * rq + p) * 68 + dq * 4 + c] = pack2(x, y);
                }
        }
        __syncthreads();

        // GEMM2 accumulate
#pragma unroll 4
        for (int f = 0; f < 64; f++) {
            u64 hp0 = hsPu[(2 * rq) * 68 + f];               // 1-wf bcast
            u64 hp1 = hsPu[(2 * rq + 1) * 68 + f];           // 1-wf bcast
            float4 wv = *(float4*)&W2c[f * 64 + dq * 4];     // 2 wf
            u64 w0 = pack_dup(wv.x), w1 = pack_dup(wv.y);
            u64 w2 = pack_dup(wv.z), w3 = pack_dup(wv.w);
            ffma2(acc2[0][0], hp0, w0); ffma2(acc2[0][1], hp0, w1);
            ffma2(acc2[0][2], hp0, w2); ffma2(acc2[0][3], hp0, w3);
            ffma2(acc2[1][0], hp1, w0); ffma2(acc2[1][1], hp1, w1);
            ffma2(acc2[1][2], hp1, w2); ffma2(acc2[1][3], hp1, w3);
        }
    }

    // Epilogue: unpack row-pairs, add bias, store 4 rows.
    float4 bb = *(float4*)&b2s[dq * 4];
#pragma unroll
    for (int p = 0; p < 2; p++) {
        float4 oa, ob;
        unpack2(acc2[p][0], oa.x, ob.x);
        unpack2(acc2[p][1], oa.y, ob.y);
        unpack2(acc2[p][2], oa.z, ob.z);
        unpack2(acc2[p][3], oa.w, ob.w);
        oa.x += bb.x; oa.y += bb.y; oa.z += bb.z; oa.w += bb.w;
        ob.x += bb.x; ob.y += bb.y; ob.z += bb.z; ob.w += bb.w;
        *(float4*)&out[(size_t)(row0 + 2 * (2 * rq + p)) * 64 + dq * 4]     = oa;
        *(float4*)&out[(size_t)(row0 + 2 * (2 * rq + p) + 1) * 64 + dq * 4] = ob;
    }
}

// ---------------------------------------------------------------------------
static const int SMEM1 = 4096 * 4 + 64 * ESTR * 8;                              // 50,176 B
static const int SMEM2 = (1024 + 128) * 8 + (LSEQ * HS + 800 + 816 + 16) * 4 + LSEQ * 4; // 70,944 B
static const int SMEM3 = 4096 * 4 * 2 + (32 * 65 + 32 * 68) * 8 + (256 + 64) * 4; // 68,096 B

extern "C" void kernel_launch(void* const* d_in, const int* in_sizes, int n_in,
                              void* d_out, int out_size) {
    const int*   his = (const int*)  d_in[0];
    const float* E   = (const float*)d_in[1];
    const float* S   = (const float*)d_in[2];
    const float* B0  = (const float*)d_in[3];
    const float* W1  = (const float*)d_in[4];
    const float* b1  = (const float*)d_in[5];
    const float* W2  = (const float*)d_in[6];
    const float* b2  = (const float*)d_in[7];
    float* out = (float*)d_out;

    cudaFuncSetAttribute(k_es,    cudaFuncAttributeMaxDynamicSharedMemorySize, SMEM1);
    cudaFuncSetAttribute(k_route, cudaFuncAttributeMaxDynamicSharedMemorySize, SMEM2);
    cudaFuncSetAttribute(k_mlp,   cudaFuncAttributeMaxDynamicSharedMemorySize, SMEM3);

    k_es<<<(VOCAB + 127) / 128, 256, SMEM1>>>(E, S);
    k_route<<<BS, 256, SMEM2>>>(his, B0);
    k_mlp<<<(BS * 4) / 64, 256, SMEM3>>>(W1, b1, W2, b2, out);
}

// round 16
// speedup vs baseline: 1.1808x; 1.0608x over previous
#include <cuda_runtime.h>
#include <math.h>
#include <float.h>

#define BS    4096
#define LSEQ  200
#define VOCAB 100000
#define ESTR  66    // k_es EsmT u64 row stride
#define HS    68    // hisP float row stride

typedef unsigned long long u64;

// ---- packed fp32x2 helpers (Blackwell FFMA2 path) ----
__device__ __forceinline__ u64 pack2(float x, float y) {
    u64 r; asm("mov.b64 %0, {%1, %2};" : "=l"(r) : "f"(x), "f"(y)); return r;
}
__device__ __forceinline__ u64 pack_dup(float x) {
    u64 r; asm("mov.b64 %0, {%1, %1};" : "=l"(r) : "f"(x)); return r;
}
__device__ __forceinline__ void unpack2(u64 v, float& x, float& y) {
    asm("mov.b64 {%0, %1}, %2;" : "=f"(x), "=f"(y) : "l"(v));
}
__device__ __forceinline__ void ffma2(u64& d, u64 a, u64 b) {
    asm("fma.rn.f32x2 %0, %1, %2, %0;" : "+l"(d) : "l"(a), "l"(b));
}
__device__ __forceinline__ u64 fadd2(u64 a, u64 b) {
    u64 r; asm("add.rn.f32x2 %0, %1, %2;" : "=l"(r) : "l"(a), "l"(b)); return r;
}

// Scratch (allocation-free: device globals)
__device__ float g_ES[VOCAB * 64];            // 25.6 MB: E @ S, row 0 zeroed
__device__ float g_caps[BS * 4 * 64];         // 4 MB: routing output

// ---------------------------------------------------------------------------
// Kernel 1: ES = E @ S (champion config; unroll 8 for deeper load-ahead).
// ---------------------------------------------------------------------------
__global__ __launch_bounds__(256, 4) void k_es(const float* __restrict__ E,
                                               const float* __restrict__ S) {
    extern __shared__ float sm[];
    float* Ssm  = sm;                        // 64*64
    u64*   EsmT = (u64*)(sm + 4096);         // [64 e][66] u64 row-pairs
    const int tid = threadIdx.x;
    const int v0 = blockIdx.x * 128;

    for (int i = tid; i < 1024; i += 256)
        ((float4*)Ssm)[i] = ((const float4*)S)[i];
    for (int i = tid; i < 1024; i += 256) {
        int rp = i >> 4, e4 = i & 15;
        int vA = v0 + 2 * rp, vB = vA + 1;
        float4 a = make_float4(0.f, 0.f, 0.f, 0.f), bv = a;
        if (vA < VOCAB) a  = *(const float4*)&E[(size_t)vA * 64 + e4 * 4];
        if (vB < VOCAB) bv = *(const float4*)&E[(size_t)vB * 64 + e4 * 4];
        EsmT[(4 * e4 + 0) * ESTR + rp] = pack2(a.x, bv.x);
        EsmT[(4 * e4 + 1) * ESTR + rp] = pack2(a.y, bv.y);
        EsmT[(4 * e4 + 2) * ESTR + rp] = pack2(a.z, bv.z);
        EsmT[(4 * e4 + 3) * ESTR + rp] = pack2(a.w, bv.w);
    }
    __syncthreads();

    const int vg = tid >> 4;
    const int dg = tid & 15;
    u64 acc[4][4];
#pragma unroll
    for (int q = 0; q < 4; q++)
#pragma unroll
        for (int c = 0; c < 4; c++) acc[q][c] = 0ull;

#pragma unroll 8
    for (int e = 0; e < 64; e++) {
        float4 sv = *(float4*)&Ssm[e * 64 + dg * 4];
        u64 sd[4];
        sd[0] = pack_dup(sv.x); sd[1] = pack_dup(sv.y);
        sd[2] = pack_dup(sv.z); sd[3] = pack_dup(sv.w);
        ulonglong2 eA = *(ulonglong2*)&EsmT[e * ESTR + vg * 4];
        ulonglong2 eB = *(ulonglong2*)&EsmT[e * ESTR + vg * 4 + 2];
#pragma unroll
        for (int c = 0; c < 4; c++) {
            ffma2(acc[0][c], eA.x, sd[c]);
            ffma2(acc[1][c], eA.y, sd[c]);
            ffma2(acc[2][c], eB.x, sd[c]);
            ffma2(acc[3][c], eB.y, sd[c]);
        }
    }

#pragma unroll
    for (int q = 0; q < 4; q++) {
        int vA = v0 + vg * 8 + 2 * q, vB = vA + 1;
        float4 oa, ob;
        unpack2(acc[q][0], oa.x, ob.x);
        unpack2(acc[q][1], oa.y, ob.y);
        unpack2(acc[q][2], oa.z, ob.z);
        unpack2(acc[q][3], oa.w, ob.w);
        if (vA < VOCAB) {
            if (vA == 0) oa = make_float4(0.f, 0.f, 0.f, 0.f);
            *(float4*)&g_ES[(size_t)vA * 64 + dg * 4] = oa;
        }
        if (vB < VOCAB) {
            *(float4*)&g_ES[(size_t)vB * 64 + dg * 4] = ob;
        }
    }
}

// ---------------------------------------------------------------------------
// Kernel 2: routing. B-update now amortizes capsP broadcasts over 2 l/thread
// (warps 0-3 only; warps 4-7 skip). Everything else = champion.
// ---------------------------------------------------------------------------
__global__ __launch_bounds__(256, 3) void k_route(const int* __restrict__ his,
                                                  const float* __restrict__ B0) {
    extern __shared__ u64 smu[];
    u64*   part2 = smu;                        // [8 lc][k*32+dp]  1024 u64
    u64*   capsP = part2 + 1024;               // [k][dp] pair-packed caps  128 u64
    float* hisP  = (float*)(capsP + 128);      // [200][68] floats
    float* Bk    = hisP + LSEQ * HS;           // [k][l] 800
    float* WkF   = Bk + 800;                   // [l][4k] plain exp floats  800+pad
    float* msum  = WkF + 816;                  // 8
    float* ssum  = msum + 8;                   // 8
    int*   idx   = (int*)(ssum + 8);           // 200

    const int tid  = threadIdx.x;
    const int b    = blockIdx.x;
    const int lane = tid & 31;
    const int w    = tid >> 5;
    const float DROPV = -2147483648.0f;

    for (int l = tid; l < LSEQ; l += 256) idx[l] = his[b * LSEQ + l];
    for (int t = tid; t < 4 * LSEQ; t += 256) Bk[t] = B0[t];
    __syncthreads();

    for (int t = tid; t < LSEQ * 16; t += 256) {
        int l = t >> 4, dq = t & 15;
        float4 v = *(const float4*)&g_ES[(size_t)idx[l] * 64 + dq * 4];
        *(float4*)&hisP[l * HS + dq * 4] = v;
    }
    __syncthreads();

    for (int it = 0; it < 3; it++) {
        // ---- split softmax: warp w handles k = w>>1, half = w&1 (100 l) ----
        {
            const int k = w >> 1;
            const int base = (w & 1) * 100;
            float m = -FLT_MAX;
            for (int j = lane; j < 100; j += 32) {
                int l = base + j;
                float v = (idx[l] != 0) ? Bk[k * LSEQ + l] : DROPV;
                m = fmaxf(m, v);
            }
#pragma unroll
            for (int o = 16; o > 0; o >>= 1) m = fmaxf(m, __shfl_xor_sync(0xffffffffu, m, o));
            float s = 0.f;
            for (int j = lane; j < 100; j += 32) {
                int l = base + j;
                float v = (idx[l] != 0) ? Bk[k * LSEQ + l] : DROPV;
                float e = __expf(v - m);
                WkF[l * 4 + k] = e;
                s += e;
            }
#pragma unroll
            for (int o = 16; o > 0; o >>= 1) s += __shfl_xor_sync(0xffffffffu, s, o);
            if (lane == 0) { msum[w] = m; ssum[w] = s; }
        }
        __syncthreads();

        // ---- caps partials: ALL 8 warps. warp = l-chunk (25 l), lane = dp ----
        {
            const int l0 = w * 25;
            u64 a0 = 0ull, a1 = 0ull, a2 = 0ull, a3 = 0ull;
#pragma unroll 5
            for (int j = 0; j < 25; j++) {
                const int l = l0 + j;
                u64 h2 = *(u64*)&hisP[l * HS + 2 * lane];   // LDS.64, conflict-free
                float4 wl = *(float4*)&WkF[l * 4];          // 1-wf broadcast
                ffma2(a0, h2, pack_dup(wl.x));
                ffma2(a1, h2, pack_dup(wl.y));
                ffma2(a2, h2, pack_dup(wl.z));
                ffma2(a3, h2, pack_dup(wl.w));
            }
            part2[w * 128 +  0 + lane] = a0;
            part2[w * 128 + 32 + lane] = a1;
            part2[w * 128 + 64 + lane] = a2;
            part2[w * 128 + 96 + lane] = a3;
        }
        __syncthreads();

        // ---- reduce (chunks 0-3 = half0, 4-7 = half1), combine, squash ----
        if (tid < 128) {
            const int k  = tid >> 5;
            const int dp = tid & 31;
            u64 cl = part2[k * 32 + dp];
#pragma unroll
            for (int lc = 1; lc < 4; lc++) cl = fadd2(cl, part2[lc * 128 + k * 32 + dp]);
            u64 ch = part2[4 * 128 + k * 32 + dp];
#pragma unroll
            for (int lc = 5; lc < 8; lc++) ch = fadd2(ch, part2[lc * 128 + k * 32 + dp]);

            float m0 = msum[2 * k], m1 = msum[2 * k + 1];
            float s0 = ssum[2 * k], s1 = ssum[2 * k + 1];
            float M  = fmaxf(m0, m1);
            float g0 = __expf(m0 - M), g1 = __expf(m1 - M);
            float Sinv = 1.f / (s0 * g0 + s1 * g1);
            float f0 = g0 * Sinv, f1 = g1 * Sinv;

            float lx, ly, hx, hy;
            unpack2(cl, lx, ly);
            unpack2(ch, hx, hy);
            float cx = lx * f0 + hx * f1;
            float cy = ly * f0 + hy * f1;

            float sq = cx * cx + cy * cy;
#pragma unroll
            for (int o = 16; o > 0; o >>= 1) sq += __shfl_xor_sync(0xffffffffu, sq, o);
            float n2 = sq;
            float n  = sqrtf(n2);
            float scale = n2 / ((1.f + n2) * n + 1e-9f);
            cx *= scale; cy *= scale;
            if (it == 2) {
                *(float2*)&g_caps[b * 256 + k * 64 + 2 * dp] = make_float2(cx, cy);
            } else {
                capsP[k * 32 + dp] = pack2(cx, cy);
            }
        }
        if (it == 2) break;
        __syncthreads();

        // ---- B-update: warps 0-3; thread t handles l = t and l = t+100 ----
        if (tid < 128) {
            const int l = (tid < 100) ? tid : 99;          // lanes 100-127 redundant
            u64 sA0 = 0ull, sA1 = 0ull, sA2 = 0ull, sA3 = 0ull;
            u64 sB0 = 0ull, sB1 = 0ull, sB2 = 0ull, sB3 = 0ull;
#pragma unroll 4
            for (int dq = 0; dq < 16; dq++) {
                ulonglong2 hA = *(ulonglong2*)&hisP[l * HS + dq * 4];
                ulonglong2 hB = *(ulonglong2*)&hisP[(l + 100) * HS + dq * 4];
                ulonglong2 c0 = *(ulonglong2*)&capsP[0 * 32 + 2 * dq];
                ulonglong2 c1 = *(ulonglong2*)&capsP[1 * 32 + 2 * dq];
                ulonglong2 c2 = *(ulonglong2*)&capsP[2 * 32 + 2 * dq];
                ulonglong2 c3 = *(ulonglong2*)&capsP[3 * 32 + 2 * dq];
                ffma2(sA0, hA.x, c0.x); ffma2(sA0, hA.y, c0.y);
                ffma2(sA1, hA.x, c1.x); ffma2(sA1, hA.y, c1.y);
                ffma2(sA2, hA.x, c2.x); ffma2(sA2, hA.y, c2.y);
                ffma2(sA3, hA.x, c3.x); ffma2(sA3, hA.y, c3.y);
                ffma2(sB0, hB.x, c0.x); ffma2(sB0, hB.y, c0.y);
                ffma2(sB1, hB.x, c1.x); ffma2(sB1, hB.y, c1.y);
                ffma2(sB2, hB.x, c2.x); ffma2(sB2, hB.y, c2.y);
                ffma2(sB3, hB.x, c3.x); ffma2(sB3, hB.y, c3.y);
            }
            if (tid < 100) {
                float x, y;
                unpack2(sA0, x, y); Bk[0 * LSEQ + l] += x + y;
                unpack2(sA1, x, y); Bk[1 * LSEQ + l] += x + y;
                unpack2(sA2, x, y); Bk[2 * LSEQ + l] += x + y;
                unpack2(sA3, x, y); Bk[3 * LSEQ + l] += x + y;
                unpack2(sB0, x, y); Bk[0 * LSEQ + l + 100] += x + y;
                unpack2(sB1, x, y); Bk[1 * LSEQ + l + 100] += x + y;
                unpack2(sB2, x, y); Bk[2 * LSEQ + l + 100] += x + y;
                unpack2(sB3, x, y); Bk[3 * LSEQ + l + 100] += x + y;
            }
        }
        __syncthreads();
    }
}

// ---------------------------------------------------------------------------
// Kernel 3: batched MLP (R15 champion, unchanged). 256 CTAs x 64 rows.
// ---------------------------------------------------------------------------
__global__ __launch_bounds__(256, 3) void k_mlp(const float* __restrict__ W1,
                                                const float* __restrict__ b1,
                                                const float* __restrict__ W2,
                                                const float* __restrict__ b2,
                                                float* __restrict__ out) {
    extern __shared__ float sm[];
    float* W1c  = sm;                          // [64 e][64 f]  16KB
    float* W2c  = W1c + 4096;                  // [64 f][64 d]  16KB
    u64*   csPu = (u64*)(W2c + 4096);          // [32 rp][65 e] u64 pairs
    u64*   hsPu = csPu + 32 * 65;              // [32 rp][68 f] u64 pairs
    float* b1s  = (float*)(hsPu + 32 * 68);    // 256
    float* b2s  = b1s + 256;                   // 64
    const int tid  = threadIdx.x;
    const int row0 = blockIdx.x * 64;

    for (int i = tid; i < 512; i += 256) {
        const int rp = i >> 4, e4 = i & 15;
        float4 a = *(const float4*)&g_caps[(size_t)(row0 + 2 * rp) * 64 + e4 * 4];
        float4 c = *(const float4*)&g_caps[(size_t)(row0 + 2 * rp + 1) * 64 + e4 * 4];
        csPu[rp * 65 + e4 * 4 + 0] = pack2(a.x, c.x);
        csPu[rp * 65 + e4 * 4 + 1] = pack2(a.y, c.y);
        csPu[rp * 65 + e4 * 4 + 2] = pack2(a.z, c.z);
        csPu[rp * 65 + e4 * 4 + 3] = pack2(a.w, c.w);
    }
    if (tid < 256) b1s[tid] = b1[tid];
    if (tid < 64)  b2s[tid] = b2[tid];

    const int rq = tid >> 4;
    const int dq = tid & 15;
    u64 acc2[2][4];
#pragma unroll
    for (int p = 0; p < 2; p++)
#pragma unroll
        for (int c = 0; c < 4; c++) acc2[p][c] = 0ull;

    for (int ch = 0; ch < 4; ch++) {
        const int f0 = ch * 64;
        __syncthreads();
        for (int i4 = tid; i4 < 1024; i4 += 256) {
            int e = i4 >> 4, j4 = i4 & 15;
            ((float4*)W1c)[i4] = *(const float4*)&W1[e * 256 + f0 + j4 * 4];
        }
        for (int i4 = tid; i4 < 1024; i4 += 256)
            ((float4*)W2c)[i4] = ((const float4*)&W2[f0 * 64])[i4];
        __syncthreads();

        {
            u64 acc1[2][4];
#pragma unroll
            for (int p = 0; p < 2; p++)
#pragma unroll
                for (int c = 0; c < 4; c++) acc1[p][c] = 0ull;
#pragma unroll 4
            for (int e = 0; e < 64; e++) {
                u64 cp0 = csPu[(2 * rq) * 65 + e];
                u64 cp1 = csPu[(2 * rq + 1) * 65 + e];
                float4 wv = *(float4*)&W1c[e * 64 + dq * 4];
                u64 w0 = pack_dup(wv.x), w1 = pack_dup(wv.y);
                u64 w2 = pack_dup(wv.z), w3 = pack_dup(wv.w);
                ffma2(acc1[0][0], cp0, w0); ffma2(acc1[0][1], cp0, w1);
                ffma2(acc1[0][2], cp0, w2); ffma2(acc1[0][3], cp0, w3);
                ffma2(acc1[1][0], cp1, w0); ffma2(acc1[1][1], cp1, w1);
                ffma2(acc1[1][2], cp1, w2); ffma2(acc1[1][3], cp1, w3);
            }
#pragma unroll
            for (int p = 0; p < 2; p++)
#pragma unroll
                for (int c = 0; c < 4; c++) {
                    float x, y;
                    unpack2(acc1[p][c], x, y);
                    float bb = b1s[f0 + dq * 4 + c];
                    x = fmaxf(x + bb, 0.f);
                    y = fmaxf(y + bb, 0.f);
                    hsPu[(2 * rq + p) * 68 + dq * 4 + c] = pack2(x, y);
                }
        }
        __syncthreads();

#pragma unroll 4
        for (int f = 0; f < 64; f++) {
            u64 hp0 = hsPu[(2 * rq) * 68 + f];
            u64 hp1 = hsPu[(2 * rq + 1) * 68 + f];
            float4 wv = *(float4*)&W2c[f * 64 + dq * 4];
            u64 w0 = pack_dup(wv.x), w1 = pack_dup(wv.y);
            u64 w2 = pack_dup(wv.z), w3 = pack_dup(wv.w);
            ffma2(acc2[0][0], hp0, w0); ffma2(acc2[0][1], hp0, w1);
            ffma2(acc2[0][2], hp0, w2); ffma2(acc2[0][3], hp0, w3);
            ffma2(acc2[1][0], hp1, w0); ffma2(acc2[1][1], hp1, w1);
            ffma2(acc2[1][2], hp1, w2); ffma2(acc2[1][3], hp1, w3);
        }
    }

    float4 bb = *(float4*)&b2s[dq * 4];
#pragma unroll
    for (int p = 0; p < 2; p++) {
        float4 oa, ob;
        unpack2(acc2[p][0], oa.x, ob.x);
        unpack2(acc2[p][1], oa.y, ob.y);
        unpack2(acc2[p][2], oa.z, ob.z);
        unpack2(acc2[p][3], oa.w, ob.w);
        oa.x += bb.x; oa.y += bb.y; oa.z += bb.z; oa.w += bb.w;
        ob.x += bb.x; ob.y += bb.y; ob.z += bb.z; ob.w += bb.w;
        *(float4*)&out[(size_t)(row0 + 2 * (2 * rq + p)) * 64 + dq * 4]     = oa;
        *(float4*)&out[(size_t)(row0 + 2 * (2 * rq + p) + 1) * 64 + dq * 4] = ob;
    }
}

// ---------------------------------------------------------------------------
static const int SMEM1 = 4096 * 4 + 64 * ESTR * 8;                              // 50,176 B
static const int SMEM2 = (1024 + 128) * 8 + (LSEQ * HS + 800 + 816 + 16) * 4 + LSEQ * 4; // 70,944 B
static const int SMEM3 = 4096 * 4 * 2 + (32 * 65 + 32 * 68) * 8 + (256 + 64) * 4; // 68,096 B

extern "C" void kernel_launch(void* const* d_in, const int* in_sizes, int n_in,
                              void* d_out, int out_size) {
    const int*   his = (const int*)  d_in[0];
    const float* E   = (const float*)d_in[1];
    const float* S   = (const float*)d_in[2];
    const float* B0  = (const float*)d_in[3];
    const float* W1  = (const float*)d_in[4];
    const float* b1  = (const float*)d_in[5];
    const float* W2  = (const float*)d_in[6];
    const float* b2  = (const float*)d_in[7];
    float* out = (float*)d_out;

    cudaFuncSetAttribute(k_es,    cudaFuncAttributeMaxDynamicSharedMemorySize, SMEM1);
    cudaFuncSetAttribute(k_route, cudaFuncAttributeMaxDynamicSharedMemorySize, SMEM2);
    cudaFuncSetAttribute(k_mlp,   cudaFuncAttributeMaxDynamicSharedMemorySize, SMEM3);

    k_es<<<(VOCAB + 127) / 128, 256, SMEM1>>>(E, S);
    k_route<<<BS, 256, SMEM2>>>(his, B0);
    k_mlp<<<(BS * 4) / 64, 256, SMEM3>>>(W1, b1, W2, b2, out);
}

// round 17
// speedup vs baseline: 1.2035x; 1.0192x over previous
#include <cuda_runtime.h>
#include <math.h>
#include <float.h>

#define BS    4096
#define LSEQ  200
#define VOCAB 100000
#define ESTR  66    // k_es EsmT u64 row stride
#define HS    68    // hisP float row stride

typedef unsigned long long u64;

// ---- packed fp32x2 helpers (Blackwell FFMA2 path) ----
__device__ __forceinline__ u64 pack2(float x, float y) {
    u64 r; asm("mov.b64 %0, {%1, %2};" : "=l"(r) : "f"(x), "f"(y)); return r;
}
__device__ __forceinline__ u64 pack_dup(float x) {
    u64 r; asm("mov.b64 %0, {%1, %1};" : "=l"(r) : "f"(x)); return r;
}
__device__ __forceinline__ void unpack2(u64 v, float& x, float& y) {
    asm("mov.b64 {%0, %1}, %2;" : "=f"(x), "=f"(y) : "l"(v));
}
__device__ __forceinline__ void ffma2(u64& d, u64 a, u64 b) {
    asm("fma.rn.f32x2 %0, %1, %2, %0;" : "+l"(d) : "l"(a), "l"(b));
}
__device__ __forceinline__ u64 fadd2(u64 a, u64 b) {
    u64 r; asm("add.rn.f32x2 %0, %1, %2;" : "=l"(r) : "l"(a), "l"(b)); return r;
}

// Scratch (allocation-free: device globals)
__device__ float g_ES[VOCAB * 64];            // 25.6 MB: E @ S, row 0 zeroed
__device__ float g_caps[BS * 4 * 64];         // 4 MB: routing output
__device__ float g_b0max[4];                  // per-k max of B0 (softmax shift, it=0)

// ---------------------------------------------------------------------------
// Kernel 1: ES = E @ S (champion config). Block 0 also computes g_b0max.
// ---------------------------------------------------------------------------
__global__ __launch_bounds__(256, 4) void k_es(const float* __restrict__ E,
                                               const float* __restrict__ S,
                                               const float* __restrict__ B0) {
    extern __shared__ float sm[];
    float* Ssm  = sm;                        // 64*64
    u64*   EsmT = (u64*)(sm + 4096);         // [64 e][66] u64 row-pairs
    const int tid = threadIdx.x;
    const int v0 = blockIdx.x * 128;

    // block 0, warps 0-3: per-k unmasked max of B0 (valid softmax shift)
    if (blockIdx.x == 0 && tid < 128) {
        const int k = tid >> 5, lane = tid & 31;
        float m = -FLT_MAX;
        for (int l = lane; l < LSEQ; l += 32) m = fmaxf(m, B0[k * LSEQ + l]);
#pragma unroll
        for (int o = 16; o > 0; o >>= 1) m = fmaxf(m, __shfl_xor_sync(0xffffffffu, m, o));
        if (lane == 0) g_b0max[k] = m;
    }

    for (int i = tid; i < 1024; i += 256)
        ((float4*)Ssm)[i] = ((const float4*)S)[i];
    for (int i = tid; i < 1024; i += 256) {
        int rp = i >> 4, e4 = i & 15;
        int vA = v0 + 2 * rp, vB = vA + 1;
        float4 a = make_float4(0.f, 0.f, 0.f, 0.f), bv = a;
        if (vA < VOCAB) a  = *(const float4*)&E[(size_t)vA * 64 + e4 * 4];
        if (vB < VOCAB) bv = *(const float4*)&E[(size_t)vB * 64 + e4 * 4];
        EsmT[(4 * e4 + 0) * ESTR + rp] = pack2(a.x, bv.x);
        EsmT[(4 * e4 + 1) * ESTR + rp] = pack2(a.y, bv.y);
        EsmT[(4 * e4 + 2) * ESTR + rp] = pack2(a.z, bv.z);
        EsmT[(4 * e4 + 3) * ESTR + rp] = pack2(a.w, bv.w);
    }
    __syncthreads();

    const int vg = tid >> 4;
    const int dg = tid & 15;
    u64 acc[4][4];
#pragma unroll
    for (int q = 0; q < 4; q++)
#pragma unroll
        for (int c = 0; c < 4; c++) acc[q][c] = 0ull;

#pragma unroll 8
    for (int e = 0; e < 64; e++) {
        float4 sv = *(float4*)&Ssm[e * 64 + dg * 4];
        u64 sd[4];
        sd[0] = pack_dup(sv.x); sd[1] = pack_dup(sv.y);
        sd[2] = pack_dup(sv.z); sd[3] = pack_dup(sv.w);
        ulonglong2 eA = *(ulonglong2*)&EsmT[e * ESTR + vg * 4];
        ulonglong2 eB = *(ulonglong2*)&EsmT[e * ESTR + vg * 4 + 2];
#pragma unroll
        for (int c = 0; c < 4; c++) {
            ffma2(acc[0][c], eA.x, sd[c]);
            ffma2(acc[1][c], eA.y, sd[c]);
            ffma2(acc[2][c], eB.x, sd[c]);
            ffma2(acc[3][c], eB.y, sd[c]);
        }
    }

#pragma unroll
    for (int q = 0; q < 4; q++) {
        int vA = v0 + vg * 8 + 2 * q, vB = vA + 1;
        float4 oa, ob;
        unpack2(acc[q][0], oa.x, ob.x);
        unpack2(acc[q][1], oa.y, ob.y);
        unpack2(acc[q][2], oa.z, ob.z);
        unpack2(acc[q][3], oa.w, ob.w);
        if (vA < VOCAB) {
            if (vA == 0) oa = make_float4(0.f, 0.f, 0.f, 0.f);
            *(float4*)&g_ES[(size_t)vA * 64 + dg * 4] = oa;
        }
        if (vB < VOCAB) {
            *(float4*)&g_ES[(size_t)vB * 64 + dg * 4] = ob;
        }
    }
}

// ---------------------------------------------------------------------------
// Kernel 2: routing. Softmax max-pass ELIMINATED: it0 uses g_b0max; it1/it2
// use per-k maxes fused into the B-update (unmasked max = valid shift).
// ---------------------------------------------------------------------------
__global__ __launch_bounds__(256, 3) void k_route(const int* __restrict__ his,
                                                  const float* __restrict__ B0) {
    extern __shared__ u64 smu[];
    u64*   part2 = smu;                        // [8 lc][k*32+dp]  1024 u64
    u64*   capsP = part2 + 1024;               // [k][dp] pair-packed caps  128 u64
    float* hisP  = (float*)(capsP + 128);      // [200][68] floats
    float* Bk    = hisP + LSEQ * HS;           // [k][l] 800
    float* WkF   = Bk + 800;                   // [l][4k] plain exp floats  800+pad
    float* ssum  = WkF + 816;                  // 8 (per (k,half) expsum)
    float* wmax4 = ssum + 8;                   // [4 warp][4 k] B-update maxes
    int*   idx   = (int*)(wmax4 + 16);         // 200

    const int tid  = threadIdx.x;
    const int b    = blockIdx.x;
    const int lane = tid & 31;
    const int w    = tid >> 5;
    const float DROPV = -2147483648.0f;

    for (int l = tid; l < LSEQ; l += 256) idx[l] = his[b * LSEQ + l];
    for (int t = tid; t < 4 * LSEQ; t += 256) Bk[t] = B0[t];
    __syncthreads();

    for (int t = tid; t < LSEQ * 16; t += 256) {
        int l = t >> 4, dq = t & 15;
        float4 v = *(const float4*)&g_ES[(size_t)idx[l] * 64 + dq * 4];
        *(float4*)&hisP[l * HS + dq * 4] = v;
    }
    __syncthreads();

    for (int it = 0; it < 3; it++) {
        // ---- softmax exp pass only: warp w handles k = w>>1, half = w&1 ----
        {
            const int k = w >> 1;
            const int base = (w & 1) * 100;
            float m;
            if (it == 0) {
                m = g_b0max[k];
            } else {
                m = fmaxf(fmaxf(wmax4[0 * 4 + k], wmax4[1 * 4 + k]),
                          fmaxf(wmax4[2 * 4 + k], wmax4[3 * 4 + k]));
            }
            float s = 0.f;
            for (int j = lane; j < 100; j += 32) {
                int l = base + j;
                float v = (idx[l] != 0) ? Bk[k * LSEQ + l] : DROPV;
                float e = __expf(v - m);
                WkF[l * 4 + k] = e;
                s += e;
            }
#pragma unroll
            for (int o = 16; o > 0; o >>= 1) s += __shfl_xor_sync(0xffffffffu, s, o);
            if (lane == 0) ssum[w] = s;
        }
        __syncthreads();

        // ---- caps partials: ALL 8 warps. warp = l-chunk (25 l), lane = dp ----
        {
            const int l0 = w * 25;
            u64 a0 = 0ull, a1 = 0ull, a2 = 0ull, a3 = 0ull;
#pragma unroll 5
            for (int j = 0; j < 25; j++) {
                const int l = l0 + j;
                u64 h2 = *(u64*)&hisP[l * HS + 2 * lane];   // LDS.64, conflict-free
                float4 wl = *(float4*)&WkF[l * 4];          // 1-wf broadcast
                ffma2(a0, h2, pack_dup(wl.x));
                ffma2(a1, h2, pack_dup(wl.y));
                ffma2(a2, h2, pack_dup(wl.z));
                ffma2(a3, h2, pack_dup(wl.w));
            }
            part2[w * 128 +  0 + lane] = a0;
            part2[w * 128 + 32 + lane] = a1;
            part2[w * 128 + 64 + lane] = a2;
            part2[w * 128 + 96 + lane] = a3;
        }
        __syncthreads();

        // ---- reduce (chunks 0-3 = half0, 4-7 = half1), combine, squash ----
        // Both halves used the SAME shift m, so combine is just s0 + s1.
        if (tid < 128) {
            const int k  = tid >> 5;
            const int dp = tid & 31;
            u64 cl = part2[k * 32 + dp];
#pragma unroll
            for (int lc = 1; lc < 4; lc++) cl = fadd2(cl, part2[lc * 128 + k * 32 + dp]);
            u64 ch = part2[4 * 128 + k * 32 + dp];
#pragma unroll
            for (int lc = 5; lc < 8; lc++) ch = fadd2(ch, part2[lc * 128 + k * 32 + dp]);
            u64 c2 = fadd2(cl, ch);

            float Sinv = 1.f / (ssum[2 * k] + ssum[2 * k + 1]);
            float cx, cy;
            unpack2(c2, cx, cy);
            cx *= Sinv; cy *= Sinv;

            float sq = cx * cx + cy * cy;
#pragma unroll
            for (int o = 16; o > 0; o >>= 1) sq += __shfl_xor_sync(0xffffffffu, sq, o);
            float n2 = sq;
            float n  = sqrtf(n2);
            float scale = n2 / ((1.f + n2) * n + 1e-9f);
            cx *= scale; cy *= scale;
            if (it == 2) {
                *(float2*)&g_caps[b * 256 + k * 64 + 2 * dp] = make_float2(cx, cy);
            } else {
                capsP[k * 32 + dp] = pack2(cx, cy);
            }
        }
        if (it == 2) break;
        __syncthreads();

        // ---- B-update (warps 0-3, 2 l/thread) + fused per-k unmasked max ----
        if (tid < 128) {
            const int l = (tid < 100) ? tid : 99;
            u64 sA0 = 0ull, sA1 = 0ull, sA2 = 0ull, sA3 = 0ull;
            u64 sB0 = 0ull, sB1 = 0ull, sB2 = 0ull, sB3 = 0ull;
#pragma unroll 4
            for (int dq = 0; dq < 16; dq++) {
                ulonglong2 hA = *(ulonglong2*)&hisP[l * HS + dq * 4];
                ulonglong2 hB = *(ulonglong2*)&hisP[(l + 100) * HS + dq * 4];
                ulonglong2 c0 = *(ulonglong2*)&capsP[0 * 32 + 2 * dq];
                ulonglong2 c1 = *(ulonglong2*)&capsP[1 * 32 + 2 * dq];
                ulonglong2 c2 = *(ulonglong2*)&capsP[2 * 32 + 2 * dq];
                ulonglong2 c3 = *(ulonglong2*)&capsP[3 * 32 + 2 * dq];
                ffma2(sA0, hA.x, c0.x); ffma2(sA0, hA.y, c0.y);
                ffma2(sA1, hA.x, c1.x); ffma2(sA1, hA.y, c1.y);
                ffma2(sA2, hA.x, c2.x); ffma2(sA2, hA.y, c2.y);
                ffma2(sA3, hA.x, c3.x); ffma2(sA3, hA.y, c3.y);
                ffma2(sB0, hB.x, c0.x); ffma2(sB0, hB.y, c0.y);
                ffma2(sB1, hB.x, c1.x); ffma2(sB1, hB.y, c1.y);
                ffma2(sB2, hB.x, c2.x); ffma2(sB2, hB.y, c2.y);
                ffma2(sB3, hB.x, c3.x); ffma2(sB3, hB.y, c3.y);
            }
            float x, y;
            float vA0, vA1, vA2, vA3, vB0, vB1, vB2, vB3;
            unpack2(sA0, x, y); vA0 = Bk[0 * LSEQ + l] + (x + y);
            unpack2(sA1, x, y); vA1 = Bk[1 * LSEQ + l] + (x + y);
            unpack2(sA2, x, y); vA2 = Bk[2 * LSEQ + l] + (x + y);
            unpack2(sA3, x, y); vA3 = Bk[3 * LSEQ + l] + (x + y);
            unpack2(sB0, x, y); vB0 = Bk[0 * LSEQ + l + 100] + (x + y);
            unpack2(sB1, x, y); vB1 = Bk[1 * LSEQ + l + 100] + (x + y);
            unpack2(sB2, x, y); vB2 = Bk[2 * LSEQ + l + 100] + (x + y);
            unpack2(sB3, x, y); vB3 = Bk[3 * LSEQ + l + 100] + (x + y);
            if (tid < 100) {
                Bk[0 * LSEQ + l] = vA0;       Bk[1 * LSEQ + l] = vA1;
                Bk[2 * LSEQ + l] = vA2;       Bk[3 * LSEQ + l] = vA3;
                Bk[0 * LSEQ + l + 100] = vB0; Bk[1 * LSEQ + l + 100] = vB1;
                Bk[2 * LSEQ + l + 100] = vB2; Bk[3 * LSEQ + l + 100] = vB3;
            }
            // per-k unmasked max over this warp's lanes (clamped dups harmless)
            float m0 = fmaxf(vA0, vB0), m1 = fmaxf(vA1, vB1);
            float m2 = fmaxf(vA2, vB2), m3 = fmaxf(vA3, vB3);
#pragma unroll
            for (int o = 16; o > 0; o >>= 1) {
                m0 = fmaxf(m0, __shfl_xor_sync(0xffffffffu, m0, o));
                m1 = fmaxf(m1, __shfl_xor_sync(0xffffffffu, m1, o));
                m2 = fmaxf(m2, __shfl_xor_sync(0xffffffffu, m2, o));
                m3 = fmaxf(m3, __shfl_xor_sync(0xffffffffu, m3, o));
            }
            if (lane == 0) {
                wmax4[w * 4 + 0] = m0; wmax4[w * 4 + 1] = m1;
                wmax4[w * 4 + 2] = m2; wmax4[w * 4 + 3] = m3;
            }
        }
        __syncthreads();
    }
}

// ---------------------------------------------------------------------------
// Kernel 3: batched MLP (R15 champion, unchanged). 256 CTAs x 64 rows.
// ---------------------------------------------------------------------------
__global__ __launch_bounds__(256, 3) void k_mlp(const float* __restrict__ W1,
                                                const float* __restrict__ b1,
                                                const float* __restrict__ W2,
                                                const float* __restrict__ b2,
                                                float* __restrict__ out) {
    extern __shared__ float sm[];
    float* W1c  = sm;                          // [64 e][64 f]  16KB
    float* W2c  = W1c + 4096;                  // [64 f][64 d]  16KB
    u64*   csPu = (u64*)(W2c + 4096);          // [32 rp][65 e] u64 pairs
    u64*   hsPu = csPu + 32 * 65;              // [32 rp][68 f] u64 pairs
    float* b1s  = (float*)(hsPu + 32 * 68);    // 256
    float* b2s  = b1s + 256;                   // 64
    const int tid  = threadIdx.x;
    const int row0 = blockIdx.x * 64;

    for (int i = tid; i < 512; i += 256) {
        const int rp = i >> 4, e4 = i & 15;
        float4 a = *(const float4*)&g_caps[(size_t)(row0 + 2 * rp) * 64 + e4 * 4];
        float4 c = *(const float4*)&g_caps[(size_t)(row0 + 2 * rp + 1) * 64 + e4 * 4];
        csPu[rp * 65 + e4 * 4 + 0] = pack2(a.x, c.x);
        csPu[rp * 65 + e4 * 4 + 1] = pack2(a.y, c.y);
        csPu[rp * 65 + e4 * 4 + 2] = pack2(a.z, c.z);
        csPu[rp * 65 + e4 * 4 + 3] = pack2(a.w, c.w);
    }
    if (tid < 256) b1s[tid] = b1[tid];
    if (tid < 64)  b2s[tid] = b2[tid];

    const int rq = tid >> 4;
    const int dq = tid & 15;
    u64 acc2[2][4];
#pragma unroll
    for (int p = 0; p < 2; p++)
#pragma unroll
        for (int c = 0; c < 4; c++) acc2[p][c] = 0ull;

    for (int ch = 0; ch < 4; ch++) {
        const int f0 = ch * 64;
        __syncthreads();
        for (int i4 = tid; i4 < 1024; i4 += 256) {
            int e = i4 >> 4, j4 = i4 & 15;
            ((float4*)W1c)[i4] = *(const float4*)&W1[e * 256 + f0 + j4 * 4];
        }
        for (int i4 = tid; i4 < 1024; i4 += 256)
            ((float4*)W2c)[i4] = ((const float4*)&W2[f0 * 64])[i4];
        __syncthreads();

        {
            u64 acc1[2][4];
#pragma unroll
            for (int p = 0; p < 2; p++)
#pragma unroll
                for (int c = 0; c < 4; c++) acc1[p][c] = 0ull;
#pragma unroll 4
            for (int e = 0; e < 64; e++) {
                u64 cp0 = csPu[(2 * rq) * 65 + e];
                u64 cp1 = csPu[(2 * rq + 1) * 65 + e];
                float4 wv = *(float4*)&W1c[e * 64 + dq * 4];
                u64 w0 = pack_dup(wv.x), w1 = pack_dup(wv.y);
                u64 w2 = pack_dup(wv.z), w3 = pack_dup(wv.w);
                ffma2(acc1[0][0], cp0, w0); ffma2(acc1[0][1], cp0, w1);
                ffma2(acc1[0][2], cp0, w2); ffma2(acc1[0][3], cp0, w3);
                ffma2(acc1[1][0], cp1, w0); ffma2(acc1[1][1], cp1, w1);
                ffma2(acc1[1][2], cp1, w2); ffma2(acc1[1][3], cp1, w3);
            }
#pragma unroll
            for (int p = 0; p < 2; p++)
#pragma unroll
                for (int c = 0; c < 4; c++) {
                    float x, y;
                    unpack2(acc1[p][c], x, y);
                    float bb = b1s[f0 + dq * 4 + c];
                    x = fmaxf(x + bb, 0.f);
                    y = fmaxf(y + bb, 0.f);
                    hsPu[(2 * rq + p) * 68 + dq * 4 + c] = pack2(x, y);
                }
        }
        __syncthreads();

#pragma unroll 4
        for (int f = 0; f < 64; f++) {
            u64 hp0 = hsPu[(2 * rq) * 68 + f];
            u64 hp1 = hsPu[(2 * rq + 1) * 68 + f];
            float4 wv = *(float4*)&W2c[f * 64 + dq * 4];
            u64 w0 = pack_dup(wv.x), w1 = pack_dup(wv.y);
            u64 w2 = pack_dup(wv.z), w3 = pack_dup(wv.w);
            ffma2(acc2[0][0], hp0, w0); ffma2(acc2[0][1], hp0, w1);
            ffma2(acc2[0][2], hp0, w2); ffma2(acc2[0][3], hp0, w3);
            ffma2(acc2[1][0], hp1, w0); ffma2(acc2[1][1], hp1, w1);
            ffma2(acc2[1][2], hp1, w2); ffma2(acc2[1][3], hp1, w3);
        }
    }

    float4 bb = *(float4*)&b2s[dq * 4];
#pragma unroll
    for (int p = 0; p < 2; p++) {
        float4 oa, ob;
        unpack2(acc2[p][0], oa.x, ob.x);
        unpack2(acc2[p][1], oa.y, ob.y);
        unpack2(acc2[p][2], oa.z, ob.z);
        unpack2(acc2[p][3], oa.w, ob.w);
        oa.x += bb.x; oa.y += bb.y; oa.z += bb.z; oa.w += bb.w;
        ob.x += bb.x; ob.y += bb.y; ob.z += bb.z; ob.w += bb.w;
        *(float4*)&out[(size_t)(row0 + 2 * (2 * rq + p)) * 64 + dq * 4]     = oa;
        *(float4*)&out[(size_t)(row0 + 2 * (2 * rq + p) + 1) * 64 + dq * 4] = ob;
    }
}

// ---------------------------------------------------------------------------
static const int SMEM1 = 4096 * 4 + 64 * ESTR * 8;                              // 50,176 B
static const int SMEM2 = (1024 + 128) * 8 + (LSEQ * HS + 800 + 816 + 24) * 4 + LSEQ * 4; // 70,976 B
static const int SMEM3 = 4096 * 4 * 2 + (32 * 65 + 32 * 68) * 8 + (256 + 64) * 4; // 68,096 B

extern "C" void kernel_launch(void* const* d_in, const int* in_sizes, int n_in,
                              void* d_out, int out_size) {
    const int*   his = (const int*)  d_in[0];
    const float* E   = (const float*)d_in[1];
    const float* S   = (const float*)d_in[2];
    const float* B0  = (const float*)d_in[3];
    const float* W1  = (const float*)d_in[4];
    const float* b1  = (const float*)d_in[5];
    const float* W2  = (const float*)d_in[6];
    const float* b2  = (const float*)d_in[7];
    float* out = (float*)d_out;

    cudaFuncSetAttribute(k_es,    cudaFuncAttributeMaxDynamicSharedMemorySize, SMEM1);
    cudaFuncSetAttribute(k_route, cudaFuncAttributeMaxDynamicSharedMemorySize, SMEM2);
    cudaFuncSetAttribute(k_mlp,   cudaFuncAttributeMaxDynamicSharedMemorySize, SMEM3);

    k_es<<<(VOCAB + 127) / 128, 256, SMEM1>>>(E, S, B0);
    k_route<<<BS, 256, SMEM2>>>(his, B0);
    k_mlp<<<(BS * 4) / 64, 256, SMEM3>>>(W1, b1, W2, b2, out);
}